// round 3
// baseline (speedup 1.0000x reference)
#include <cuda_runtime.h>
#include <math.h>

#define NNODES 10000
#define NEDGES 64000
#define IN_DIM 1247
#define NH 4
#define DD0 256
#define DD1 8
#define OUTD 6
#define HD0 1024   /* NH*DD0 */
#define HD1 32     /* NH*DD1 */

// ------------------- scratch (device globals; no allocation allowed) ---------
__device__ float g_colsum[IN_DIM];
__device__ float g_h[(size_t)NNODES * IN_DIM];
__device__ float g_W2p[IN_DIM * HD1];
__device__ float g_fs0[(size_t)NNODES * HD0];
__device__ float g_fd0[(size_t)NNODES * HD0];
__device__ float g_res0[(size_t)NNODES * HD0];
__device__ float g_x1[(size_t)NNODES * HD0];
__device__ float g_z2[NNODES * HD1];
__device__ float g_fs1[NNODES * HD1];
__device__ float g_fd1[NNODES * HD1];
__device__ float g_res1[NNODES * HD1];
__device__ float g_h3[NNODES * HD1];
__device__ float g_out1[NNODES * HD1];
__device__ float g_es2[NNODES * NH];
__device__ float g_ed2[NNODES * NH];
__device__ float g_lg0[NEDGES * NH];
__device__ float g_lg1[NEDGES * NH];
__device__ float g_lg2[NEDGES * NH];
__device__ int   g_deg[NNODES];
__device__ int   g_fill[NNODES];
__device__ int   g_csr_off[NNODES + 1];
__device__ int   g_csr_edge[NEDGES];

__device__ __forceinline__ float lrelu(float x) { return x > 0.f ? x : 0.2f * x; }

// ------------------- preprocessing ------------------------------------------
__global__ void zeroKernel() {
    int i = blockIdx.x * 256 + threadIdx.x;
    if (i < IN_DIM) g_colsum[i] = 0.f;
    if (i < NNODES) { g_deg[i] = 0; g_fill[i] = 0; }
}

__global__ void colsumKernel(const float* __restrict__ f) {
    int j = blockIdx.x * 256 + threadIdx.x;
    if (j >= IN_DIM) return;
    float s = 0.f;
    for (int i = blockIdx.y; i < NNODES; i += gridDim.y)
        s += f[(size_t)i * IN_DIM + j];
    atomicAdd(&g_colsum[j], s);
}

// h = 0.5*(f + (f==0 ? mean : f)); L1 normalize per row; multiply combined mask
__global__ void preprocessKernel(const float* __restrict__ f,
                                 const float* __restrict__ tm,
                                 const float* __restrict__ am,
                                 const float* __restrict__ vm) {
    __shared__ float sh[IN_DIM];
    __shared__ float red[8];
    int n = blockIdx.x;
    int t = threadIdx.x;
    const float* row = f + (size_t)n * IN_DIM;
    const float invN = 1.f / (float)NNODES;
    float s = 0.f;
    for (int j = t; j < IN_DIM; j += 256) {
        float v = row[j];
        v = (v == 0.f) ? (0.5f * g_colsum[j] * invN) : v;
        sh[j] = v;
        s += fabsf(v);
    }
    for (int off = 16; off; off >>= 1) s += __shfl_down_sync(0xffffffffu, s, off);
    if ((t & 31) == 0) red[t >> 5] = s;
    __syncthreads();
    if (t == 0) {
        float tot = 0.f;
        for (int w = 0; w < 8; w++) tot += red[w];
        red[0] = 1.f / fmaxf(tot, 1e-12f);
    }
    __syncthreads();
    float inv = red[0];
    float* out = g_h + (size_t)n * IN_DIM;
    for (int j = t; j < IN_DIM; j += 256)
        out[j] = sh[j] * inv * (tm[j] + am[j] + vm[j]);
}

// W2 [H][IN][8] -> packed [IN][32]
__global__ void packW2Kernel(const float* __restrict__ W2) {
    int idx = blockIdx.x * 256 + threadIdx.x;
    if (idx >= IN_DIM * HD1) return;
    int k = idx / HD1, c = idx % HD1;
    int h = c / DD1, o = c % DD1;
    g_W2p[idx] = W2[(size_t)h * IN_DIM * DD1 + (size_t)k * DD1 + o];
}

// ------------------- CSR build ----------------------------------------------
__global__ void histKernel(const int* __restrict__ dst) {
    int e = blockIdx.x * 256 + threadIdx.x;
    if (e < NEDGES) atomicAdd(&g_deg[dst[e]], 1);
}

__global__ void scanKernel() {
    __shared__ int sums[1024];
    const int CH = (NNODES + 1023) / 1024;  // 10
    int t = threadIdx.x;
    int base = t * CH;
    int local[CH];
    int s = 0;
    for (int i = 0; i < CH; i++) {
        int v = (base + i < NNODES) ? g_deg[base + i] : 0;
        local[i] = s;
        s += v;
    }
    sums[t] = s;
    __syncthreads();
    for (int off = 1; off < 1024; off <<= 1) {
        int v = (t >= off) ? sums[t - off] : 0;
        __syncthreads();
        sums[t] += v;
        __syncthreads();
    }
    int excl = (t == 0) ? 0 : sums[t - 1];
    for (int i = 0; i < CH; i++)
        if (base + i < NNODES) g_csr_off[base + i] = excl + local[i];
    if (t == 1023) g_csr_off[NNODES] = sums[1023];
}

__global__ void fillCsrKernel(const int* __restrict__ dst) {
    int e = blockIdx.x * 256 + threadIdx.x;
    if (e >= NEDGES) return;
    int d = dst[e];
    int pos = atomicAdd(&g_fill[d], 1);
    g_csr_edge[g_csr_off[d] + pos] = e;
}

// ------------------- fp32 tiled SGEMM ---------------------------------------
// C[Mrows x Ncols] = A[Mrows x K] * B[K x Ncols]; all row-major.
template <int BM, int BN, int BK, int TM, int TN>
__global__ void sgemmKernel(const float* __restrict__ A, int K,
                            const float* __restrict__ B, int ldb,
                            float* __restrict__ C, int ldc,
                            int Mrows, int Ncols) {
    __shared__ float As[BK][BM + 1];
    __shared__ float Bs[BK][BN];
    const int TX = BN / TN;
    int tid = threadIdx.x;
    int tx = tid % TX, ty = tid / TX;
    int r0 = blockIdx.x * BM, c0 = blockIdx.y * BN;
    float acc[TM][TN];
#pragma unroll
    for (int i = 0; i < TM; i++)
#pragma unroll
        for (int j = 0; j < TN; j++) acc[i][j] = 0.f;

    for (int k0 = 0; k0 < K; k0 += BK) {
#pragma unroll 4
        for (int idx = tid; idx < BM * BK; idx += 256) {
            int m = idx / BK, k = idx % BK;
            int gr = r0 + m, gk = k0 + k;
            As[k][m] = (gr < Mrows && gk < K) ? A[(size_t)gr * K + gk] : 0.f;
        }
#pragma unroll 4
        for (int idx = tid; idx < BK * BN; idx += 256) {
            int k = idx / BN, c = idx % BN;
            int gk = k0 + k, gc = c0 + c;
            Bs[k][c] = (gk < K && gc < Ncols) ? B[(size_t)gk * ldb + gc] : 0.f;
        }
        __syncthreads();
#pragma unroll
        for (int k = 0; k < BK; k++) {
            float a[TM], b[TN];
#pragma unroll
            for (int i = 0; i < TM; i++) a[i] = As[k][ty * TM + i];
#pragma unroll
            for (int j = 0; j < TN; j++) b[j] = Bs[k][tx * TN + j];
#pragma unroll
            for (int i = 0; i < TM; i++)
#pragma unroll
                for (int j = 0; j < TN; j++) acc[i][j] = fmaf(a[i], b[j], acc[i][j]);
        }
        __syncthreads();
    }
#pragma unroll
    for (int i = 0; i < TM; i++) {
        int gr = r0 + ty * TM + i;
        if (gr >= Mrows) continue;
#pragma unroll
        for (int j = 0; j < TN; j++) {
            int gc = c0 + tx * TN + j;
            if (gc < Ncols) C[(size_t)gr * ldc + gc] = acc[i][j];
        }
    }
}

// ------------------- gat_inner (h3) ------------------------------------------
__global__ void innerNodeTermsKernel(const float* __restrict__ a2) {
    int idx = blockIdx.x * 256 + threadIdx.x;
    if (idx >= NNODES * NH) return;
    int n = idx / NH, h = idx % NH;
    const float* z = g_z2 + n * HD1 + h * DD1;
    float es = 0.f, ed = 0.f;
#pragma unroll
    for (int o = 0; o < DD1; o++) {
        es = fmaf(z[o], a2[h * 2 * DD1 + o], es);
        ed = fmaf(z[o], a2[h * 2 * DD1 + DD1 + o], ed);
    }
    g_es2[idx] = es;
    g_ed2[idx] = ed;
}

__global__ void innerEdgeLogitsKernel(const int* __restrict__ src,
                                      const int* __restrict__ dst) {
    int idx = blockIdx.x * 256 + threadIdx.x;
    if (idx >= NEDGES * NH) return;
    int e = idx / NH, h = idx % NH;
    g_lg2[idx] = lrelu(g_es2[src[e] * NH + h] + g_ed2[dst[e] * NH + h]);
}

// in-place segment softmax over dst segments: lg -> alpha
__global__ void segSoftmaxKernel(float* __restrict__ lg) {
    int idx = blockIdx.x * 256 + threadIdx.x;
    if (idx >= NNODES * NH) return;
    int n = idx / NH, h = idx % NH;
    int s = g_csr_off[n], t = g_csr_off[n + 1];
    float m = -1e30f;
    for (int p = s; p < t; p++) m = fmaxf(m, lg[g_csr_edge[p] * NH + h]);
    float den = 0.f;
    for (int p = s; p < t; p++) {
        int a = g_csr_edge[p] * NH + h;
        float pv = __expf(lg[a] - m);
        den += pv;
        lg[a] = pv;
    }
    float inv = 1.f / fmaxf(den, 1e-9f);
    for (int p = s; p < t; p++) lg[g_csr_edge[p] * NH + h] *= inv;
}

// warp-per-node aggregation for 32-wide values (gat_inner + layer1)
__global__ void aggSmallKernel(const float* __restrict__ vals,
                               const float* __restrict__ lg,
                               const int* __restrict__ src,
                               const float* __restrict__ res,
                               const float* __restrict__ bias,
                               float* __restrict__ out, int doRelu) {
    int w = (blockIdx.x * blockDim.x + threadIdx.x) >> 5;
    int lane = threadIdx.x & 31;
    if (w >= NNODES) return;
    int h = lane >> 3;
    int s = g_csr_off[w], t = g_csr_off[w + 1];
    float acc = 0.f;
    for (int p = s; p < t; p++) {
        int e = g_csr_edge[p];
        acc = fmaf(lg[e * NH + h], vals[src[e] * HD1 + lane], acc);
    }
    if (res) acc += res[w * HD1 + lane] + bias[lane];
    if (doRelu) acc = fmaxf(acc, 0.f);
    out[w * HD1 + lane] = acc;
}

// ------------------- gatv2 layer 0 (D=256) ------------------------------------
__global__ void gatv2EdgeLogits0Kernel(const int* __restrict__ src,
                                       const int* __restrict__ dst,
                                       const float* __restrict__ a0) {
    int e = blockIdx.x;
    int t = threadIdx.x;  // 128
    const float4* fs = (const float4*)(g_fs0 + (size_t)src[e] * HD0);
    const float4* fd = (const float4*)(g_fd0 + (size_t)dst[e] * HD0);
    const float4* a4 = (const float4*)a0;  // a0 flat [H*256] == [1024]
    float partial = 0.f;
#pragma unroll
    for (int q = 0; q < 2; q++) {
        int i4 = t * 2 + q;
        float4 u = fs[i4], v = fd[i4], w = a4[i4];
        partial = fmaf(lrelu(u.x + v.x), w.x, partial);
        partial = fmaf(lrelu(u.y + v.y), w.y, partial);
        partial = fmaf(lrelu(u.z + v.z), w.z, partial);
        partial = fmaf(lrelu(u.w + v.w), w.w, partial);
    }
    for (int off = 16; off; off >>= 1)
        partial += __shfl_down_sync(0xffffffffu, partial, off);
    if ((t & 31) == 0) g_lg0[e * NH + (t >> 5)] = partial;
}

__global__ void gatv2Agg0Kernel(const int* __restrict__ src,
                                const float* __restrict__ b0) {
    int n = blockIdx.x;
    int t = threadIdx.x;  // 256; thread handles float4 -> elems t*4..t*4+3
    int h = t >> 6;
    int s = g_csr_off[n], e1 = g_csr_off[n + 1];
    float4 acc = make_float4(0.f, 0.f, 0.f, 0.f);
    for (int p = s; p < e1; p++) {
        int e = g_csr_edge[p];
        float a = g_lg0[e * NH + h];
        float4 v = ((const float4*)(g_fs0 + (size_t)src[e] * HD0))[t];
        acc.x = fmaf(a, v.x, acc.x);
        acc.y = fmaf(a, v.y, acc.y);
        acc.z = fmaf(a, v.z, acc.z);
        acc.w = fmaf(a, v.w, acc.w);
    }
    float4 r = ((const float4*)(g_res0 + (size_t)n * HD0))[t];
    float4 bb = ((const float4*)b0)[t];
    acc.x = fmaxf(acc.x + r.x + bb.x, 0.f);
    acc.y = fmaxf(acc.y + r.y + bb.y, 0.f);
    acc.z = fmaxf(acc.z + r.z + bb.z, 0.f);
    acc.w = fmaxf(acc.w + r.w + bb.w, 0.f);
    ((float4*)(g_x1 + (size_t)n * HD0))[t] = acc;
}

// ------------------- gatv2 layer 1 (D=8) --------------------------------------
__global__ void gatv2EdgeLogits1Kernel(const int* __restrict__ src,
                                       const int* __restrict__ dst,
                                       const float* __restrict__ a1) {
    int w = (blockIdx.x * blockDim.x + threadIdx.x) >> 5;
    int lane = threadIdx.x & 31;
    if (w >= NEDGES) return;
    float x = g_fs1[src[w] * HD1 + lane] + g_fd1[dst[w] * HD1 + lane];
    float p = lrelu(x) * a1[lane];  // a1 flat [H][8] == [32]
    p += __shfl_down_sync(0xffffffffu, p, 4, 8);
    p += __shfl_down_sync(0xffffffffu, p, 2, 8);
    p += __shfl_down_sync(0xffffffffu, p, 1, 8);
    if ((lane & 7) == 0) g_lg1[w * NH + (lane >> 3)] = p;
}

// ------------------- final linear ---------------------------------------------
__global__ void finalLinearKernel(const float* __restrict__ Wlin,
                                  const float* __restrict__ blin,
                                  float* __restrict__ out) {
    int n = blockIdx.x * 256 + threadIdx.x;
    if (n >= NNODES) return;
    float acc[OUTD];
#pragma unroll
    for (int c = 0; c < OUTD; c++) acc[c] = blin[c];
#pragma unroll 4
    for (int j = 0; j < HD1; j++) {
        float v = g_h3[n * HD1 + j];
#pragma unroll
        for (int c = 0; c < OUTD; c++) acc[c] = fmaf(v, Wlin[j * OUTD + c], acc[c]);
    }
#pragma unroll 4
    for (int j = 0; j < HD1; j++) {
        float v = g_out1[n * HD1 + j];
#pragma unroll
        for (int c = 0; c < OUTD; c++)
            acc[c] = fmaf(v, Wlin[(HD1 + j) * OUTD + c], acc[c]);
    }
#pragma unroll
    for (int c = 0; c < OUTD; c++) out[n * OUTD + c] = acc[c];
}

// ------------------- launch ---------------------------------------------------
extern "C" void kernel_launch(void* const* d_in, const int* in_sizes, int n_in,
                              void* d_out, int out_size) {
    const float* features = (const float*)d_in[0];
    const int* src = (const int*)d_in[1];
    const int* dst = (const int*)d_in[2];
    const float* textMask = (const float*)d_in[3];
    const float* audioMask = (const float*)d_in[4];
    const float* videoMask = (const float*)d_in[5];
    const float* W2 = (const float*)d_in[6];
    const float* a2 = (const float*)d_in[7];
    const float* Wl0 = (const float*)d_in[8];
    const float* Wr0 = (const float*)d_in[9];
    const float* a0 = (const float*)d_in[10];
    const float* Wres0 = (const float*)d_in[11];
    const float* b0 = (const float*)d_in[12];
    const float* Wl1 = (const float*)d_in[13];
    const float* Wr1 = (const float*)d_in[14];
    const float* a1 = (const float*)d_in[15];
    const float* Wres1 = (const float*)d_in[16];
    const float* b1 = (const float*)d_in[17];
    const float* Wlin = (const float*)d_in[18];
    const float* blin = (const float*)d_in[19];
    float* out = (float*)d_out;

    float *p_h, *p_fs0, *p_fd0, *p_res0, *p_x1, *p_z2, *p_fs1, *p_fd1, *p_res1;
    float *p_W2p, *p_lg0, *p_lg1, *p_lg2, *p_h3, *p_out1;
    cudaGetSymbolAddress((void**)&p_h, g_h);
    cudaGetSymbolAddress((void**)&p_fs0, g_fs0);
    cudaGetSymbolAddress((void**)&p_fd0, g_fd0);
    cudaGetSymbolAddress((void**)&p_res0, g_res0);
    cudaGetSymbolAddress((void**)&p_x1, g_x1);
    cudaGetSymbolAddress((void**)&p_z2, g_z2);
    cudaGetSymbolAddress((void**)&p_fs1, g_fs1);
    cudaGetSymbolAddress((void**)&p_fd1, g_fd1);
    cudaGetSymbolAddress((void**)&p_res1, g_res1);
    cudaGetSymbolAddress((void**)&p_W2p, g_W2p);
    cudaGetSymbolAddress((void**)&p_lg0, g_lg0);
    cudaGetSymbolAddress((void**)&p_lg1, g_lg1);
    cudaGetSymbolAddress((void**)&p_lg2, g_lg2);
    cudaGetSymbolAddress((void**)&p_h3, g_h3);
    cudaGetSymbolAddress((void**)&p_out1, g_out1);

    // 1) preprocessing
    zeroKernel<<<(NNODES + 255) / 256, 256>>>();
    {
        dim3 g((IN_DIM + 255) / 256, 40);
        colsumKernel<<<g, 256>>>(features);
    }
    preprocessKernel<<<NNODES, 256>>>(features, textMask, audioMask, videoMask);
    packW2Kernel<<<(IN_DIM * HD1 + 255) / 256, 256>>>(W2);

    // 2) CSR build
    histKernel<<<(NEDGES + 255) / 256, 256>>>(dst);
    scanKernel<<<1, 1024>>>();
    fillCsrKernel<<<(NEDGES + 255) / 256, 256>>>(dst);

    // 3) big GEMMs from h: [10000 x 1247] x [1247 x 1024]
    {
        dim3 g((NNODES + 127) / 128, (HD0 + 127) / 128);
        sgemmKernel<128, 128, 16, 8, 8><<<g, 256>>>(p_h, IN_DIM, Wl0, HD0, p_fs0, HD0, NNODES, HD0);
        sgemmKernel<128, 128, 16, 8, 8><<<g, 256>>>(p_h, IN_DIM, Wr0, HD0, p_fd0, HD0, NNODES, HD0);
        sgemmKernel<128, 128, 16, 8, 8><<<g, 256>>>(p_h, IN_DIM, Wres0, HD0, p_res0, HD0, NNODES, HD0);
    }
    // z2 = h @ W2packed : [10000 x 1247] x [1247 x 32]
    {
        dim3 g((NNODES + 127) / 128, 1);
        sgemmKernel<128, 32, 16, 8, 2><<<g, 256>>>(p_h, IN_DIM, p_W2p, HD1, p_z2, HD1, NNODES, HD1);
    }

    // 4) gat_inner -> h3
    innerNodeTermsKernel<<<(NNODES * NH + 255) / 256, 256>>>(a2);
    innerEdgeLogitsKernel<<<(NEDGES * NH + 255) / 256, 256>>>(src, dst);
    segSoftmaxKernel<<<(NNODES * NH + 255) / 256, 256>>>(p_lg2);
    aggSmallKernel<<<(NNODES * 32 + 255) / 256, 256>>>(p_z2, p_lg2, src, (const float*)0,
                                                       (const float*)0, p_h3, 0);

    // 5) gatv2 layer 0 -> x1
    gatv2EdgeLogits0Kernel<<<NEDGES, 128>>>(src, dst, a0);
    segSoftmaxKernel<<<(NNODES * NH + 255) / 256, 256>>>(p_lg0);
    gatv2Agg0Kernel<<<NNODES, 256>>>(src, b0);

    // 6) layer-1 projections: [10000 x 1024] x [1024 x 32]
    {
        dim3 g((NNODES + 127) / 128, 1);
        sgemmKernel<128, 32, 16, 8, 2><<<g, 256>>>(p_x1, HD0, Wl1, HD1, p_fs1, HD1, NNODES, HD1);
        sgemmKernel<128, 32, 16, 8, 2><<<g, 256>>>(p_x1, HD0, Wr1, HD1, p_fd1, HD1, NNODES, HD1);
        sgemmKernel<128, 32, 16, 8, 2><<<g, 256>>>(p_x1, HD0, Wres1, HD1, p_res1, HD1, NNODES, HD1);
    }

    // 7) gatv2 layer 1 -> out1
    gatv2EdgeLogits1Kernel<<<(NEDGES * 32 + 255) / 256, 256>>>(src, dst, a1);
    segSoftmaxKernel<<<(NNODES * NH + 255) / 256, 256>>>(p_lg1);
    aggSmallKernel<<<(NNODES * 32 + 255) / 256, 256>>>(p_fs1, p_lg1, src, p_res1, b1, p_out1, 1);

    // 8) final linear
    finalLinearKernel<<<(NNODES + 255) / 256, 256>>>(Wlin, blin, out);
}

// round 4
// speedup vs baseline: 1.4762x; 1.4762x over previous
#include <cuda_runtime.h>
#include <math.h>
#include <stdint.h>

#define NNODES 10000
#define NEDGES 64000
#define IN_DIM 1247
#define NH 4
#define DD0 256
#define DD1 8
#define OUTD 6
#define HD0 1024   /* NH*DD0 */
#define HD1 32     /* NH*DD1 */
#define L1W 96     /* 3*HD1 packed layer-1 outputs */

// ------------------- scratch (device globals; no allocation allowed) ---------
__device__ float g_colsum[IN_DIM];
__device__ float g_h[(size_t)NNODES * IN_DIM];
__device__ float g_W2p[IN_DIM * HD1];
__device__ float g_Wcat[HD0 * L1W];
__device__ float g_fs0[(size_t)NNODES * HD0];
__device__ float g_fd0[(size_t)NNODES * HD0];
__device__ float g_res0[(size_t)NNODES * HD0];
__device__ float g_x1[(size_t)NNODES * HD0];
__device__ float g_z2[NNODES * HD1];
__device__ float g_l1out[(size_t)NNODES * L1W];   /* fs1|fd1|res1 */
__device__ float g_h3[NNODES * HD1];
__device__ float g_out1[NNODES * HD1];
__device__ float g_es2[NNODES * NH];
__device__ float g_ed2[NNODES * NH];
__device__ float g_lg0[NEDGES * NH];
__device__ float g_lg1[NEDGES * NH];
__device__ float g_lg2[NEDGES * NH];
__device__ int   g_deg[NNODES];
__device__ int   g_fill[NNODES];
__device__ int   g_csr_off[NNODES + 1];
__device__ int   g_csr_edge[NEDGES];

__device__ __forceinline__ float lrelu(float x) { return x > 0.f ? x : 0.2f * x; }
__device__ __forceinline__ float to_tf32(float x) {
    float r;
    asm("cvt.rna.tf32.f32 %0, %1;" : "=f"(r) : "f"(x));
    return r;
}

// ------------------- preprocessing ------------------------------------------
__global__ void zeroKernel() {
    int i = blockIdx.x * 256 + threadIdx.x;
    if (i < IN_DIM) g_colsum[i] = 0.f;
    if (i < NNODES) { g_deg[i] = 0; g_fill[i] = 0; }
}

__global__ void colsumKernel(const float* __restrict__ f) {
    int j = blockIdx.x * 256 + threadIdx.x;
    if (j >= IN_DIM) return;
    float s = 0.f;
    for (int i = blockIdx.y; i < NNODES; i += gridDim.y)
        s += f[(size_t)i * IN_DIM + j];
    atomicAdd(&g_colsum[j], s);
}

__global__ void preprocessKernel(const float* __restrict__ f,
                                 const float* __restrict__ tm,
                                 const float* __restrict__ am,
                                 const float* __restrict__ vm) {
    __shared__ float sh[IN_DIM];
    __shared__ float red[8];
    int n = blockIdx.x;
    int t = threadIdx.x;
    const float* row = f + (size_t)n * IN_DIM;
    const float invN = 1.f / (float)NNODES;
    float s = 0.f;
    for (int j = t; j < IN_DIM; j += 256) {
        float v = row[j];
        v = (v == 0.f) ? (0.5f * g_colsum[j] * invN) : v;
        sh[j] = v;
        s += fabsf(v);
    }
    for (int off = 16; off; off >>= 1) s += __shfl_down_sync(0xffffffffu, s, off);
    if ((t & 31) == 0) red[t >> 5] = s;
    __syncthreads();
    if (t == 0) {
        float tot = 0.f;
        for (int w = 0; w < 8; w++) tot += red[w];
        red[0] = 1.f / fmaxf(tot, 1e-12f);
    }
    __syncthreads();
    float inv = red[0];
    float* out = g_h + (size_t)n * IN_DIM;
    for (int j = t; j < IN_DIM; j += 256)
        out[j] = sh[j] * inv * (tm[j] + am[j] + vm[j]);
}

// W2 [H][IN][8] -> packed [IN][32]
__global__ void packW2Kernel(const float* __restrict__ W2) {
    int idx = blockIdx.x * 256 + threadIdx.x;
    if (idx >= IN_DIM * HD1) return;
    int k = idx / HD1, c = idx % HD1;
    int h = c / DD1, o = c % DD1;
    g_W2p[idx] = W2[(size_t)h * IN_DIM * DD1 + (size_t)k * DD1 + o];
}

// Wl1|Wr1|Wres1 -> [1024][96]
__global__ void packWcatKernel(const float* __restrict__ Wl1,
                               const float* __restrict__ Wr1,
                               const float* __restrict__ Wres1) {
    int idx = blockIdx.x * 256 + threadIdx.x;
    if (idx >= HD0 * L1W) return;
    int k = idx / L1W, c = idx % L1W;
    float v;
    if (c < HD1) v = Wl1[k * HD1 + c];
    else if (c < 2 * HD1) v = Wr1[k * HD1 + (c - HD1)];
    else v = Wres1[k * HD1 + (c - 2 * HD1)];
    g_Wcat[idx] = v;
}

// ------------------- CSR build ----------------------------------------------
__global__ void histKernel(const int* __restrict__ dst) {
    int e = blockIdx.x * 256 + threadIdx.x;
    if (e < NEDGES) atomicAdd(&g_deg[dst[e]], 1);
}

__global__ void scanKernel() {
    __shared__ int sums[1024];
    const int CH = (NNODES + 1023) / 1024;
    int t = threadIdx.x;
    int base = t * CH;
    int local[CH];
    int s = 0;
    for (int i = 0; i < CH; i++) {
        int v = (base + i < NNODES) ? g_deg[base + i] : 0;
        local[i] = s;
        s += v;
    }
    sums[t] = s;
    __syncthreads();
    for (int off = 1; off < 1024; off <<= 1) {
        int v = (t >= off) ? sums[t - off] : 0;
        __syncthreads();
        sums[t] += v;
        __syncthreads();
    }
    int excl = (t == 0) ? 0 : sums[t - 1];
    for (int i = 0; i < CH; i++)
        if (base + i < NNODES) g_csr_off[base + i] = excl + local[i];
    if (t == 1023) g_csr_off[NNODES] = sums[1023];
}

__global__ void fillCsrKernel(const int* __restrict__ dst) {
    int e = blockIdx.x * 256 + threadIdx.x;
    if (e >= NEDGES) return;
    int d = dst[e];
    int pos = atomicAdd(&g_fill[d], 1);
    g_csr_edge[g_csr_off[d] + pos] = e;
}

// ------------------- TF32 tensor-core GEMM -----------------------------------
// C[Mrows x Ncols] = A[Mrows x K] * B[K x Ncols], row-major, fp32 I/O,
// tf32 mma.sync.m16n8k8 with fp32 accumulation.
// Block 128x128x32, 8 warps (2 m x 4 n), warp tile 64x32.
#define BMt 128
#define BNt 128
#define BKt 32
#define SPAD 4

__global__ __launch_bounds__(256) void tf32GemmKernel(
    const float* __restrict__ A, int K,
    const float* __restrict__ B, int ldb,
    float* __restrict__ C, int ldc, int Mrows, int Ncols) {
    __shared__ float As[BMt][BKt + SPAD];
    __shared__ float Bs[BNt][BKt + SPAD];  // B transposed: Bs[n][k]
    int tid = threadIdx.x;
    int lane = tid & 31;
    int w = tid >> 5;
    int wm = w & 1, wn = w >> 1;
    int g = lane >> 2, tg = lane & 3;
    int r0 = blockIdx.x * BMt, c0 = blockIdx.y * BNt;

    float acc[4][4][4];
#pragma unroll
    for (int i = 0; i < 4; i++)
#pragma unroll
        for (int j = 0; j < 4; j++)
#pragma unroll
            for (int r = 0; r < 4; r++) acc[i][j][r] = 0.f;

    int nK = (K + BKt - 1) / BKt;
    for (int kt = 0; kt < nK; kt++) {
        int k0 = kt * BKt;
        // A tile: scalar loads (row stride K may be 16B-misaligned)
#pragma unroll 4
        for (int i = tid; i < BMt * BKt / 2; i += 256) {
            int row = i / (BKt / 2);
            int q = i % (BKt / 2);
            int gr = r0 + row;
            int gk0 = k0 + q * 2;
            float v0 = 0.f, v1 = 0.f;
            if (gr < Mrows) {
                const float* ap = A + (size_t)gr * K;
                if (gk0 < K) v0 = ap[gk0];
                if (gk0 + 1 < K) v1 = ap[gk0 + 1];
            }
            As[row][q * 2] = to_tf32(v0);
            As[row][q * 2 + 1] = to_tf32(v1);
        }
        // B tile: float4 along n (ldb % 4 == 0 for all call sites)
#pragma unroll 4
        for (int i = tid; i < BKt * (BNt / 4); i += 256) {
            int k = i >> 5;             // 0..31
            int q = i & 31;             // float4 index along n
            int gk = k0 + k, gn = c0 + q * 4;
            float4 v = make_float4(0.f, 0.f, 0.f, 0.f);
            if (gk < K) {
                if (gn + 3 < Ncols) {
                    v = *(const float4*)(B + (size_t)gk * ldb + gn);
                } else {
                    const float* bp = B + (size_t)gk * ldb;
                    if (gn < Ncols) v.x = bp[gn];
                    if (gn + 1 < Ncols) v.y = bp[gn + 1];
                    if (gn + 2 < Ncols) v.z = bp[gn + 2];
                }
            }
            Bs[q * 4 + 0][k] = to_tf32(v.x);
            Bs[q * 4 + 1][k] = to_tf32(v.y);
            Bs[q * 4 + 2][k] = to_tf32(v.z);
            Bs[q * 4 + 3][k] = to_tf32(v.w);
        }
        __syncthreads();
#pragma unroll
        for (int ks = 0; ks < 4; ks++) {
            int kk = ks * 8;
            uint32_t a[4][4], b[4][2];
#pragma unroll
            for (int mf = 0; mf < 4; mf++) {
                int row = wm * 64 + mf * 16 + g;
                a[mf][0] = __float_as_uint(As[row][kk + tg]);
                a[mf][1] = __float_as_uint(As[row + 8][kk + tg]);
                a[mf][2] = __float_as_uint(As[row][kk + tg + 4]);
                a[mf][3] = __float_as_uint(As[row + 8][kk + tg + 4]);
            }
#pragma unroll
            for (int nf = 0; nf < 4; nf++) {
                int col = wn * 32 + nf * 8 + g;
                b[nf][0] = __float_as_uint(Bs[col][kk + tg]);
                b[nf][1] = __float_as_uint(Bs[col][kk + tg + 4]);
            }
#pragma unroll
            for (int mf = 0; mf < 4; mf++)
#pragma unroll
                for (int nf = 0; nf < 4; nf++) {
                    asm volatile(
                        "mma.sync.aligned.m16n8k8.row.col.f32.tf32.tf32.f32 "
                        "{%0,%1,%2,%3}, {%4,%5,%6,%7}, {%8,%9}, {%0,%1,%2,%3};"
                        : "+f"(acc[mf][nf][0]), "+f"(acc[mf][nf][1]),
                          "+f"(acc[mf][nf][2]), "+f"(acc[mf][nf][3])
                        : "r"(a[mf][0]), "r"(a[mf][1]), "r"(a[mf][2]), "r"(a[mf][3]),
                          "r"(b[nf][0]), "r"(b[nf][1]));
                }
        }
        __syncthreads();
    }
    // epilogue
#pragma unroll
    for (int mf = 0; mf < 4; mf++) {
        int rA = r0 + wm * 64 + mf * 16 + g;
        int rB = rA + 8;
#pragma unroll
        for (int nf = 0; nf < 4; nf++) {
            int gc = c0 + wn * 32 + nf * 8 + tg * 2;
            if (gc < Ncols) {
                if (rA < Mrows) C[(size_t)rA * ldc + gc] = acc[mf][nf][0];
                if (rB < Mrows) C[(size_t)rB * ldc + gc] = acc[mf][nf][2];
            }
            if (gc + 1 < Ncols) {
                if (rA < Mrows) C[(size_t)rA * ldc + gc + 1] = acc[mf][nf][1];
                if (rB < Mrows) C[(size_t)rB * ldc + gc + 1] = acc[mf][nf][3];
            }
        }
    }
}

// ------------------- gat_inner (h3) ------------------------------------------
__global__ void innerNodeTermsKernel(const float* __restrict__ a2) {
    int idx = blockIdx.x * 256 + threadIdx.x;
    if (idx >= NNODES * NH) return;
    int n = idx / NH, h = idx % NH;
    const float* z = g_z2 + n * HD1 + h * DD1;
    float es = 0.f, ed = 0.f;
#pragma unroll
    for (int o = 0; o < DD1; o++) {
        es = fmaf(z[o], a2[h * 2 * DD1 + o], es);
        ed = fmaf(z[o], a2[h * 2 * DD1 + DD1 + o], ed);
    }
    g_es2[idx] = es;
    g_ed2[idx] = ed;
}

__global__ void innerEdgeLogitsKernel(const int* __restrict__ src,
                                      const int* __restrict__ dst) {
    int idx = blockIdx.x * 256 + threadIdx.x;
    if (idx >= NEDGES * NH) return;
    int e = idx / NH, h = idx % NH;
    g_lg2[idx] = lrelu(g_es2[src[e] * NH + h] + g_ed2[dst[e] * NH + h]);
}

// in-place segment softmax over dst segments
__global__ void segSoftmaxKernel(float* __restrict__ lg) {
    int idx = blockIdx.x * 256 + threadIdx.x;
    if (idx >= NNODES * NH) return;
    int n = idx / NH, h = idx % NH;
    int s = g_csr_off[n], t = g_csr_off[n + 1];
    float m = -1e30f;
    for (int p = s; p < t; p++) m = fmaxf(m, lg[g_csr_edge[p] * NH + h]);
    float den = 0.f;
    for (int p = s; p < t; p++) {
        int a = g_csr_edge[p] * NH + h;
        float pv = __expf(lg[a] - m);
        den += pv;
        lg[a] = pv;
    }
    float inv = 1.f / fmaxf(den, 1e-9f);
    for (int p = s; p < t; p++) lg[g_csr_edge[p] * NH + h] *= inv;
}

// warp-per-node aggregation for 32-wide values; strides parametric
__global__ void aggSmallKernel(const float* __restrict__ vals, int vstride,
                               const float* __restrict__ lg,
                               const int* __restrict__ src,
                               const float* __restrict__ res, int rstride,
                               const float* __restrict__ bias,
                               float* __restrict__ out, int doRelu) {
    int w = (blockIdx.x * blockDim.x + threadIdx.x) >> 5;
    int lane = threadIdx.x & 31;
    if (w >= NNODES) return;
    int h = lane >> 3;
    int s = g_csr_off[w], t = g_csr_off[w + 1];
    float acc = 0.f;
    for (int p = s; p < t; p++) {
        int e = g_csr_edge[p];
        acc = fmaf(lg[e * NH + h], vals[src[e] * vstride + lane], acc);
    }
    if (res) acc += res[w * rstride + lane] + bias[lane];
    if (doRelu) acc = fmaxf(acc, 0.f);
    out[w * HD1 + lane] = acc;
}

// ------------------- gatv2 layer 0 (D=256) ------------------------------------
__global__ void gatv2EdgeLogits0Kernel(const int* __restrict__ src,
                                       const int* __restrict__ dst,
                                       const float* __restrict__ a0) {
    int e = blockIdx.x;
    int t = threadIdx.x;  // 128
    const float4* fs = (const float4*)(g_fs0 + (size_t)src[e] * HD0);
    const float4* fd = (const float4*)(g_fd0 + (size_t)dst[e] * HD0);
    const float4* a4 = (const float4*)a0;
    float partial = 0.f;
#pragma unroll
    for (int q = 0; q < 2; q++) {
        int i4 = t * 2 + q;
        float4 u = fs[i4], v = fd[i4], w = a4[i4];
        partial = fmaf(lrelu(u.x + v.x), w.x, partial);
        partial = fmaf(lrelu(u.y + v.y), w.y, partial);
        partial = fmaf(lrelu(u.z + v.z), w.z, partial);
        partial = fmaf(lrelu(u.w + v.w), w.w, partial);
    }
    for (int off = 16; off; off >>= 1)
        partial += __shfl_down_sync(0xffffffffu, partial, off);
    if ((t & 31) == 0) g_lg0[e * NH + (t >> 5)] = partial;
}

__global__ void gatv2Agg0Kernel(const int* __restrict__ src,
                                const float* __restrict__ b0) {
    int n = blockIdx.x;
    int t = threadIdx.x;  // 256
    int h = t >> 6;
    int s = g_csr_off[n], e1 = g_csr_off[n + 1];
    float4 acc = make_float4(0.f, 0.f, 0.f, 0.f);
    for (int p = s; p < e1; p++) {
        int e = g_csr_edge[p];
        float a = g_lg0[e * NH + h];
        float4 v = ((const float4*)(g_fs0 + (size_t)src[e] * HD0))[t];
        acc.x = fmaf(a, v.x, acc.x);
        acc.y = fmaf(a, v.y, acc.y);
        acc.z = fmaf(a, v.z, acc.z);
        acc.w = fmaf(a, v.w, acc.w);
    }
    float4 r = ((const float4*)(g_res0 + (size_t)n * HD0))[t];
    float4 bb = ((const float4*)b0)[t];
    acc.x = fmaxf(acc.x + r.x + bb.x, 0.f);
    acc.y = fmaxf(acc.y + r.y + bb.y, 0.f);
    acc.z = fmaxf(acc.z + r.z + bb.z, 0.f);
    acc.w = fmaxf(acc.w + r.w + bb.w, 0.f);
    ((float4*)(g_x1 + (size_t)n * HD0))[t] = acc;
}

// ------------------- gatv2 layer 1 (D=8) --------------------------------------
__global__ void gatv2EdgeLogits1Kernel(const int* __restrict__ src,
                                       const int* __restrict__ dst,
                                       const float* __restrict__ a1) {
    int w = (blockIdx.x * blockDim.x + threadIdx.x) >> 5;
    int lane = threadIdx.x & 31;
    if (w >= NEDGES) return;
    float x = g_l1out[(size_t)src[w] * L1W + lane] +
              g_l1out[(size_t)dst[w] * L1W + HD1 + lane];
    float p = lrelu(x) * a1[lane];
    p += __shfl_down_sync(0xffffffffu, p, 4, 8);
    p += __shfl_down_sync(0xffffffffu, p, 2, 8);
    p += __shfl_down_sync(0xffffffffu, p, 1, 8);
    if ((lane & 7) == 0) g_lg1[w * NH + (lane >> 3)] = p;
}

// ------------------- final linear ---------------------------------------------
__global__ void finalLinearKernel(const float* __restrict__ Wlin,
                                  const float* __restrict__ blin,
                                  float* __restrict__ out) {
    int n = blockIdx.x * 256 + threadIdx.x;
    if (n >= NNODES) return;
    float acc[OUTD];
#pragma unroll
    for (int c = 0; c < OUTD; c++) acc[c] = blin[c];
#pragma unroll 4
    for (int j = 0; j < HD1; j++) {
        float v = g_h3[n * HD1 + j];
#pragma unroll
        for (int c = 0; c < OUTD; c++) acc[c] = fmaf(v, Wlin[j * OUTD + c], acc[c]);
    }
#pragma unroll 4
    for (int j = 0; j < HD1; j++) {
        float v = g_out1[n * HD1 + j];
#pragma unroll
        for (int c = 0; c < OUTD; c++)
            acc[c] = fmaf(v, Wlin[(HD1 + j) * OUTD + c], acc[c]);
    }
#pragma unroll
    for (int c = 0; c < OUTD; c++) out[n * OUTD + c] = acc[c];
}

// ------------------- launch ---------------------------------------------------
extern "C" void kernel_launch(void* const* d_in, const int* in_sizes, int n_in,
                              void* d_out, int out_size) {
    const float* features = (const float*)d_in[0];
    const int* src = (const int*)d_in[1];
    const int* dst = (const int*)d_in[2];
    const float* textMask = (const float*)d_in[3];
    const float* audioMask = (const float*)d_in[4];
    const float* videoMask = (const float*)d_in[5];
    const float* W2 = (const float*)d_in[6];
    const float* a2 = (const float*)d_in[7];
    const float* Wl0 = (const float*)d_in[8];
    const float* Wr0 = (const float*)d_in[9];
    const float* a0 = (const float*)d_in[10];
    const float* Wres0 = (const float*)d_in[11];
    const float* b0 = (const float*)d_in[12];
    const float* Wl1 = (const float*)d_in[13];
    const float* Wr1 = (const float*)d_in[14];
    const float* a1 = (const float*)d_in[15];
    const float* Wres1 = (const float*)d_in[16];
    const float* b1 = (const float*)d_in[17];
    const float* Wlin = (const float*)d_in[18];
    const float* blin = (const float*)d_in[19];
    float* out = (float*)d_out;

    float *p_h, *p_fs0, *p_fd0, *p_res0, *p_x1, *p_z2, *p_l1out;
    float *p_W2p, *p_Wcat, *p_lg0, *p_lg1, *p_lg2, *p_h3, *p_out1;
    cudaGetSymbolAddress((void**)&p_h, g_h);
    cudaGetSymbolAddress((void**)&p_fs0, g_fs0);
    cudaGetSymbolAddress((void**)&p_fd0, g_fd0);
    cudaGetSymbolAddress((void**)&p_res0, g_res0);
    cudaGetSymbolAddress((void**)&p_x1, g_x1);
    cudaGetSymbolAddress((void**)&p_z2, g_z2);
    cudaGetSymbolAddress((void**)&p_l1out, g_l1out);
    cudaGetSymbolAddress((void**)&p_W2p, g_W2p);
    cudaGetSymbolAddress((void**)&p_Wcat, g_Wcat);
    cudaGetSymbolAddress((void**)&p_lg0, g_lg0);
    cudaGetSymbolAddress((void**)&p_lg1, g_lg1);
    cudaGetSymbolAddress((void**)&p_lg2, g_lg2);
    cudaGetSymbolAddress((void**)&p_h3, g_h3);
    cudaGetSymbolAddress((void**)&p_out1, g_out1);

    // 1) preprocessing
    zeroKernel<<<(NNODES + 255) / 256, 256>>>();
    {
        dim3 g((IN_DIM + 255) / 256, 40);
        colsumKernel<<<g, 256>>>(features);
    }
    preprocessKernel<<<NNODES, 256>>>(features, textMask, audioMask, videoMask);
    packW2Kernel<<<(IN_DIM * HD1 + 255) / 256, 256>>>(W2);
    packWcatKernel<<<(HD0 * L1W + 255) / 256, 256>>>(Wl1, Wr1, Wres1);

    // 2) CSR build
    histKernel<<<(NEDGES + 255) / 256, 256>>>(dst);
    scanKernel<<<1, 1024>>>();
    fillCsrKernel<<<(NEDGES + 255) / 256, 256>>>(dst);

    // 3) big GEMMs (tf32 tensor): [10000 x 1247] x [1247 x 1024]
    {
        dim3 g((NNODES + BMt - 1) / BMt, (HD0 + BNt - 1) / BNt);
        tf32GemmKernel<<<g, 256>>>(p_h, IN_DIM, Wl0, HD0, p_fs0, HD0, NNODES, HD0);
        tf32GemmKernel<<<g, 256>>>(p_h, IN_DIM, Wr0, HD0, p_fd0, HD0, NNODES, HD0);
        tf32GemmKernel<<<g, 256>>>(p_h, IN_DIM, Wres0, HD0, p_res0, HD0, NNODES, HD0);
    }
    // z2 = h @ W2packed : [10000 x 1247] x [1247 x 32]
    {
        dim3 g((NNODES + BMt - 1) / BMt, 1);
        tf32GemmKernel<<<g, 256>>>(p_h, IN_DIM, p_W2p, HD1, p_z2, HD1, NNODES, HD1);
    }

    // 4) gat_inner -> h3
    innerNodeTermsKernel<<<(NNODES * NH + 255) / 256, 256>>>(a2);
    innerEdgeLogitsKernel<<<(NEDGES * NH + 255) / 256, 256>>>(src, dst);
    segSoftmaxKernel<<<(NNODES * NH + 255) / 256, 256>>>(p_lg2);
    aggSmallKernel<<<(NNODES * 32 + 255) / 256, 256>>>(p_z2, HD1, p_lg2, src,
                                                       (const float*)0, 0,
                                                       (const float*)0, p_h3, 0);

    // 5) gatv2 layer 0 -> x1
    gatv2EdgeLogits0Kernel<<<NEDGES, 128>>>(src, dst, a0);
    segSoftmaxKernel<<<(NNODES * NH + 255) / 256, 256>>>(p_lg0);
    gatv2Agg0Kernel<<<NNODES, 256>>>(src, b0);

    // 6) layer-1 projections fused: [10000 x 1024] x [1024 x 96]
    {
        dim3 g((NNODES + BMt - 1) / BMt, 1);
        tf32GemmKernel<<<g, 256>>>(p_x1, HD0, p_Wcat, L1W, p_l1out, L1W, NNODES, L1W);
    }

    // 7) gatv2 layer 1 -> out1
    gatv2EdgeLogits1Kernel<<<(NEDGES * 32 + 255) / 256, 256>>>(src, dst, a1);
    segSoftmaxKernel<<<(NNODES * NH + 255) / 256, 256>>>(p_lg1);
    aggSmallKernel<<<(NNODES * 32 + 255) / 256, 256>>>(p_l1out, L1W, p_lg1, src,
                                                       p_l1out + 2 * HD1, L1W, b1,
                                                       p_out1, 1);

    // 8) final linear
    finalLinearKernel<<<(NNODES + 255) / 256, 256>>>(Wlin, blin, out);
}

// round 5
// speedup vs baseline: 2.0940x; 1.4186x over previous
#include <cuda_runtime.h>
#include <math.h>
#include <stdint.h>

#define NNODES 10000
#define NEDGES 64000
#define IN_DIM 1247
#define NH 4
#define DD0 256
#define DD1 8
#define OUTD 6
#define HD0 1024   /* NH*DD0 */
#define HD1 32     /* NH*DD1 */
#define L1W 96     /* 3*HD1 packed layer-1 outputs */

// ------------------- scratch (device globals; no allocation allowed) ---------
__device__ float g_colsum[IN_DIM];
__device__ float g_h[(size_t)NNODES * IN_DIM];
__device__ float g_W2p[IN_DIM * HD1];
__device__ float g_Wcat[HD0 * L1W];
__device__ float g_fs0[(size_t)NNODES * HD0];
__device__ float g_fd0[(size_t)NNODES * HD0];
__device__ float g_res0[(size_t)NNODES * HD0];
__device__ float g_x1[(size_t)NNODES * HD0];
__device__ float g_z2[NNODES * HD1];
__device__ float g_l1out[(size_t)NNODES * L1W];   /* fs1|fd1|res1 */
__device__ float g_h3[NNODES * HD1];
__device__ float g_out1[NNODES * HD1];
__device__ float g_es2[NNODES * NH];
__device__ float g_ed2[NNODES * NH];
__device__ float g_lg0[NEDGES * NH];
__device__ float g_lg1[NEDGES * NH];
__device__ float g_lg2[NEDGES * NH];
__device__ int   g_deg[NNODES];
__device__ int   g_fill[NNODES];
__device__ int   g_csr_off[NNODES + 1];
__device__ int   g_csr_edge[NEDGES];

__device__ __forceinline__ float lrelu(float x) { return x > 0.f ? x : 0.2f * x; }
__device__ __forceinline__ float to_tf32(float x) {
    float r;
    asm("cvt.rna.tf32.f32 %0, %1;" : "=f"(r) : "f"(x));
    return r;
}
__device__ __forceinline__ uint32_t fau(float x) { return __float_as_uint(x); }

// ------------------- preprocessing ------------------------------------------
__global__ void zeroKernel() {
    int i = blockIdx.x * 256 + threadIdx.x;
    if (i < IN_DIM) g_colsum[i] = 0.f;
    if (i < NNODES) { g_deg[i] = 0; g_fill[i] = 0; }
}

__global__ void colsumKernel(const float* __restrict__ f) {
    int j = blockIdx.x * 256 + threadIdx.x;
    if (j >= IN_DIM) return;
    float s = 0.f;
    for (int i = blockIdx.y; i < NNODES; i += gridDim.y)
        s += f[(size_t)i * IN_DIM + j];
    atomicAdd(&g_colsum[j], s);
}

__global__ void preprocessKernel(const float* __restrict__ f,
                                 const float* __restrict__ tm,
                                 const float* __restrict__ am,
                                 const float* __restrict__ vm) {
    __shared__ float sh[IN_DIM];
    __shared__ float red[8];
    int n = blockIdx.x;
    int t = threadIdx.x;
    const float* row = f + (size_t)n * IN_DIM;
    const float invN = 1.f / (float)NNODES;
    float s = 0.f;
    for (int j = t; j < IN_DIM; j += 256) {
        float v = row[j];
        v = (v == 0.f) ? (0.5f * g_colsum[j] * invN) : v;
        sh[j] = v;
        s += fabsf(v);
    }
    for (int off = 16; off; off >>= 1) s += __shfl_down_sync(0xffffffffu, s, off);
    if ((t & 31) == 0) red[t >> 5] = s;
    __syncthreads();
    if (t == 0) {
        float tot = 0.f;
        for (int w = 0; w < 8; w++) tot += red[w];
        red[0] = 1.f / fmaxf(tot, 1e-12f);
    }
    __syncthreads();
    float inv = red[0];
    float* out = g_h + (size_t)n * IN_DIM;
    for (int j = t; j < IN_DIM; j += 256)
        out[j] = sh[j] * inv * (tm[j] + am[j] + vm[j]);
}

// W2 [H][IN][8] -> packed [IN][32]
__global__ void packW2Kernel(const float* __restrict__ W2) {
    int idx = blockIdx.x * 256 + threadIdx.x;
    if (idx >= IN_DIM * HD1) return;
    int k = idx / HD1, c = idx % HD1;
    int h = c / DD1, o = c % DD1;
    g_W2p[idx] = W2[(size_t)h * IN_DIM * DD1 + (size_t)k * DD1 + o];
}

// Wl1|Wr1|Wres1 -> [1024][96]
__global__ void packWcatKernel(const float* __restrict__ Wl1,
                               const float* __restrict__ Wr1,
                               const float* __restrict__ Wres1) {
    int idx = blockIdx.x * 256 + threadIdx.x;
    if (idx >= HD0 * L1W) return;
    int k = idx / L1W, c = idx % L1W;
    float v;
    if (c < HD1) v = Wl1[k * HD1 + c];
    else if (c < 2 * HD1) v = Wr1[k * HD1 + (c - HD1)];
    else v = Wres1[k * HD1 + (c - 2 * HD1)];
    g_Wcat[idx] = v;
}

// ------------------- CSR build ----------------------------------------------
__global__ void histKernel(const int* __restrict__ dst) {
    int e = blockIdx.x * 256 + threadIdx.x;
    if (e < NEDGES) atomicAdd(&g_deg[dst[e]], 1);
}

__global__ void scanKernel() {
    __shared__ int sums[1024];
    const int CH = (NNODES + 1023) / 1024;
    int t = threadIdx.x;
    int base = t * CH;
    int local[CH];
    int s = 0;
    for (int i = 0; i < CH; i++) {
        int v = (base + i < NNODES) ? g_deg[base + i] : 0;
        local[i] = s;
        s += v;
    }
    sums[t] = s;
    __syncthreads();
    for (int off = 1; off < 1024; off <<= 1) {
        int v = (t >= off) ? sums[t - off] : 0;
        __syncthreads();
        sums[t] += v;
        __syncthreads();
    }
    int excl = (t == 0) ? 0 : sums[t - 1];
    for (int i = 0; i < CH; i++)
        if (base + i < NNODES) g_csr_off[base + i] = excl + local[i];
    if (t == 1023) g_csr_off[NNODES] = sums[1023];
}

__global__ void fillCsrKernel(const int* __restrict__ dst) {
    int e = blockIdx.x * 256 + threadIdx.x;
    if (e >= NEDGES) return;
    int d = dst[e];
    int pos = atomicAdd(&g_fill[d], 1);
    g_csr_edge[g_csr_off[d] + pos] = e;
}

// ------------------- TF32 tensor-core GEMM (pipelined, perm-k smem) ----------
// C[M x N] = A[M x K] * B[K x N], row-major fp32 I/O, tf32 mma m16n8k8.
// Block 128x128x32, 8 warps (2m x 4n), warp tile 64x32, double-buffered smem.
// Smem layout: value k stored at column c = (k&3)*8 + (k>>2)  (row stride 36)
//   -> a lane's 8 needed k-values (k = tg + 4j) are contiguous: two LDS.128.
#define BMt 128
#define BNt 128
#define BKt 32
#define SW  36
#define GEMM_SMEM (2 * (BMt + BNt) * SW * sizeof(float))

__global__ __launch_bounds__(256) void tf32GemmKernel(
    const float* __restrict__ A, int K,
    const float* __restrict__ B, int ldb,
    float* __restrict__ C, int ldc, int Mrows, int Ncols) {
    extern __shared__ float sm[];
    float* Asb = sm;                  // [2][BMt][SW]
    float* Bsb = sm + 2 * BMt * SW;   // [2][BNt][SW]
#define AS(b, r, c) Asb[((b) * BMt + (r)) * SW + (c)]
#define BS(b, r, c) Bsb[((b) * BNt + (r)) * SW + (c)]

    int tid = threadIdx.x;
    int lane = tid & 31;
    int w = tid >> 5;
    int wm = w & 1, wn = w >> 1;
    int g = lane >> 2, tg = lane & 3;
    int r0 = blockIdx.x * BMt, c0 = blockIdx.y * BNt;

    float acc[4][4][4];
#pragma unroll
    for (int i = 0; i < 4; i++)
#pragma unroll
        for (int j = 0; j < 4; j++)
#pragma unroll
            for (int r = 0; r < 4; r++) acc[i][j][r] = 0.f;

    float aReg[16];
    float4 bReg[4];
    int nK = (K + BKt - 1) / BKt;

    // ---- prologue: load tile 0 into regs ----
    {
        int k0 = 0;
#pragma unroll
        for (int s = 0; s < 8; s++) {
            int i = s * 256 + tid;
            int row = i >> 4, q = i & 15;
            int gr = r0 + row, gk = k0 + q * 2;
            float v0 = 0.f, v1 = 0.f;
            if (gr < Mrows) {
                const float* ap = A + (size_t)gr * K;
                if (gk < K) v0 = ap[gk];
                if (gk + 1 < K) v1 = ap[gk + 1];
            }
            aReg[2 * s] = v0;
            aReg[2 * s + 1] = v1;
        }
#pragma unroll
        for (int s = 0; s < 4; s++) {
            int i = s * 256 + tid;
            int k = i & 31, q = i >> 5;
            int gk = k0 + k, gn = c0 + q * 4;
            float4 v = make_float4(0.f, 0.f, 0.f, 0.f);
            if (gk < K) {
                const float* bp = B + (size_t)gk * ldb;
                if (gn + 3 < Ncols) v = *(const float4*)(bp + gn);
                else {
                    if (gn < Ncols) v.x = bp[gn];
                    if (gn + 1 < Ncols) v.y = bp[gn + 1];
                    if (gn + 2 < Ncols) v.z = bp[gn + 2];
                }
            }
            bReg[s] = v;
        }
    }
    // STS tile 0 -> buf 0
#pragma unroll
    for (int s = 0; s < 8; s++) {
        int i = s * 256 + tid;
        int row = i >> 4, q = i & 15;
        int k1 = 2 * q, k2 = 2 * q + 1;
        AS(0, row, (k1 & 3) * 8 + (k1 >> 2)) = to_tf32(aReg[2 * s]);
        AS(0, row, (k2 & 3) * 8 + (k2 >> 2)) = to_tf32(aReg[2 * s + 1]);
    }
#pragma unroll
    for (int s = 0; s < 4; s++) {
        int i = s * 256 + tid;
        int k = i & 31, q = i >> 5;
        int ck = (k & 3) * 8 + (k >> 2);
        BS(0, q * 4 + 0, ck) = to_tf32(bReg[s].x);
        BS(0, q * 4 + 1, ck) = to_tf32(bReg[s].y);
        BS(0, q * 4 + 2, ck) = to_tf32(bReg[s].z);
        BS(0, q * 4 + 3, ck) = to_tf32(bReg[s].w);
    }
    __syncthreads();

    // ---- mainloop ----
    for (int kt = 0; kt < nK; kt++) {
        int buf = kt & 1;
        bool hasNext = (kt + 1) < nK;
        if (hasNext) {
            int k0 = (kt + 1) * BKt;
#pragma unroll
            for (int s = 0; s < 8; s++) {
                int i = s * 256 + tid;
                int row = i >> 4, q = i & 15;
                int gr = r0 + row, gk = k0 + q * 2;
                float v0 = 0.f, v1 = 0.f;
                if (gr < Mrows) {
                    const float* ap = A + (size_t)gr * K;
                    if (gk < K) v0 = ap[gk];
                    if (gk + 1 < K) v1 = ap[gk + 1];
                }
                aReg[2 * s] = v0;
                aReg[2 * s + 1] = v1;
            }
#pragma unroll
            for (int s = 0; s < 4; s++) {
                int i = s * 256 + tid;
                int k = i & 31, q = i >> 5;
                int gk = k0 + k, gn = c0 + q * 4;
                float4 v = make_float4(0.f, 0.f, 0.f, 0.f);
                if (gk < K) {
                    const float* bp = B + (size_t)gk * ldb;
                    if (gn + 3 < Ncols) v = *(const float4*)(bp + gn);
                    else {
                        if (gn < Ncols) v.x = bp[gn];
                        if (gn + 1 < Ncols) v.y = bp[gn + 1];
                        if (gn + 2 < Ncols) v.z = bp[gn + 2];
                    }
                }
                bReg[s] = v;
            }
        }

        // MMA on smem buf (two halves: half=0 -> ks 0,1 ; half=1 -> ks 2,3)
#pragma unroll
        for (int half = 0; half < 2; half++) {
            float4 Af0[4], Af1[4], Bf[4];
#pragma unroll
            for (int mf = 0; mf < 4; mf++) {
                int r = wm * 64 + mf * 16 + g;
                Af0[mf] = *(const float4*)&AS(buf, r, tg * 8 + half * 4);
                Af1[mf] = *(const float4*)&AS(buf, r + 8, tg * 8 + half * 4);
            }
#pragma unroll
            for (int nf = 0; nf < 4; nf++) {
                int cc = wn * 32 + nf * 8 + g;
                Bf[nf] = *(const float4*)&BS(buf, cc, tg * 8 + half * 4);
            }
#pragma unroll
            for (int ks2 = 0; ks2 < 2; ks2++) {
#pragma unroll
                for (int mf = 0; mf < 4; mf++) {
                    uint32_t a0, a1, a2, a3;
                    if (ks2 == 0) {
                        a0 = fau(Af0[mf].x); a1 = fau(Af1[mf].x);
                        a2 = fau(Af0[mf].y); a3 = fau(Af1[mf].y);
                    } else {
                        a0 = fau(Af0[mf].z); a1 = fau(Af1[mf].z);
                        a2 = fau(Af0[mf].w); a3 = fau(Af1[mf].w);
                    }
#pragma unroll
                    for (int nf = 0; nf < 4; nf++) {
                        uint32_t b0 = (ks2 == 0) ? fau(Bf[nf].x) : fau(Bf[nf].z);
                        uint32_t b1 = (ks2 == 0) ? fau(Bf[nf].y) : fau(Bf[nf].w);
                        asm volatile(
                            "mma.sync.aligned.m16n8k8.row.col.f32.tf32.tf32.f32 "
                            "{%0,%1,%2,%3}, {%4,%5,%6,%7}, {%8,%9}, {%0,%1,%2,%3};"
                            : "+f"(acc[mf][nf][0]), "+f"(acc[mf][nf][1]),
                              "+f"(acc[mf][nf][2]), "+f"(acc[mf][nf][3])
                            : "r"(a0), "r"(a1), "r"(a2), "r"(a3),
                              "r"(b0), "r"(b1));
                    }
                }
            }
        }

        if (hasNext) {
            int nb = buf ^ 1;
#pragma unroll
            for (int s = 0; s < 8; s++) {
                int i = s * 256 + tid;
                int row = i >> 4, q = i & 15;
                int k1 = 2 * q, k2 = 2 * q + 1;
                AS(nb, row, (k1 & 3) * 8 + (k1 >> 2)) = to_tf32(aReg[2 * s]);
                AS(nb, row, (k2 & 3) * 8 + (k2 >> 2)) = to_tf32(aReg[2 * s + 1]);
            }
#pragma unroll
            for (int s = 0; s < 4; s++) {
                int i = s * 256 + tid;
                int k = i & 31, q = i >> 5;
                int ck = (k & 3) * 8 + (k >> 2);
                BS(nb, q * 4 + 0, ck) = to_tf32(bReg[s].x);
                BS(nb, q * 4 + 1, ck) = to_tf32(bReg[s].y);
                BS(nb, q * 4 + 2, ck) = to_tf32(bReg[s].z);
                BS(nb, q * 4 + 3, ck) = to_tf32(bReg[s].w);
            }
        }
        __syncthreads();
    }

    // ---- epilogue ----
#pragma unroll
    for (int mf = 0; mf < 4; mf++) {
        int rA = r0 + wm * 64 + mf * 16 + g;
        int rB = rA + 8;
#pragma unroll
        for (int nf = 0; nf < 4; nf++) {
            int gc = c0 + wn * 32 + nf * 8 + tg * 2;
            if (gc < Ncols) {
                if (rA < Mrows) C[(size_t)rA * ldc + gc] = acc[mf][nf][0];
                if (rB < Mrows) C[(size_t)rB * ldc + gc] = acc[mf][nf][2];
            }
            if (gc + 1 < Ncols) {
                if (rA < Mrows) C[(size_t)rA * ldc + gc + 1] = acc[mf][nf][1];
                if (rB < Mrows) C[(size_t)rB * ldc + gc + 1] = acc[mf][nf][3];
            }
        }
    }
#undef AS
#undef BS
}

// ------------------- gat_inner (h3) ------------------------------------------
__global__ void innerNodeTermsKernel(const float* __restrict__ a2) {
    int idx = blockIdx.x * 256 + threadIdx.x;
    if (idx >= NNODES * NH) return;
    int n = idx / NH, h = idx % NH;
    const float* z = g_z2 + n * HD1 + h * DD1;
    float es = 0.f, ed = 0.f;
#pragma unroll
    for (int o = 0; o < DD1; o++) {
        es = fmaf(z[o], a2[h * 2 * DD1 + o], es);
        ed = fmaf(z[o], a2[h * 2 * DD1 + DD1 + o], ed);
    }
    g_es2[idx] = es;
    g_ed2[idx] = ed;
}

__global__ void innerEdgeLogitsKernel(const int* __restrict__ src,
                                      const int* __restrict__ dst) {
    int idx = blockIdx.x * 256 + threadIdx.x;
    if (idx >= NEDGES * NH) return;
    int e = idx / NH, h = idx % NH;
    g_lg2[idx] = lrelu(g_es2[src[e] * NH + h] + g_ed2[dst[e] * NH + h]);
}

// in-place segment softmax over dst segments
__global__ void segSoftmaxKernel(float* __restrict__ lg) {
    int idx = blockIdx.x * 256 + threadIdx.x;
    if (idx >= NNODES * NH) return;
    int n = idx / NH, h = idx % NH;
    int s = g_csr_off[n], t = g_csr_off[n + 1];
    float m = -1e30f;
    for (int p = s; p < t; p++) m = fmaxf(m, lg[g_csr_edge[p] * NH + h]);
    float den = 0.f;
    for (int p = s; p < t; p++) {
        int a = g_csr_edge[p] * NH + h;
        float pv = __expf(lg[a] - m);
        den += pv;
        lg[a] = pv;
    }
    float inv = 1.f / fmaxf(den, 1e-9f);
    for (int p = s; p < t; p++) lg[g_csr_edge[p] * NH + h] *= inv;
}

// warp-per-node aggregation for 32-wide values; strides parametric
__global__ void aggSmallKernel(const float* __restrict__ vals, int vstride,
                               const float* __restrict__ lg,
                               const int* __restrict__ src,
                               const float* __restrict__ res, int rstride,
                               const float* __restrict__ bias,
                               float* __restrict__ out, int doRelu) {
    int w = (blockIdx.x * blockDim.x + threadIdx.x) >> 5;
    int lane = threadIdx.x & 31;
    if (w >= NNODES) return;
    int h = lane >> 3;
    int s = g_csr_off[w], t = g_csr_off[w + 1];
    float acc = 0.f;
    for (int p = s; p < t; p++) {
        int e = g_csr_edge[p];
        acc = fmaf(lg[e * NH + h], vals[src[e] * vstride + lane], acc);
    }
    if (res) acc += res[w * rstride + lane] + bias[lane];
    if (doRelu) acc = fmaxf(acc, 0.f);
    out[w * HD1 + lane] = acc;
}

// ------------------- gatv2 layer 0 (D=256) ------------------------------------
__global__ void gatv2EdgeLogits0Kernel(const int* __restrict__ src,
                                       const int* __restrict__ dst,
                                       const float* __restrict__ a0) {
    int e = blockIdx.x;
    int t = threadIdx.x;  // 128
    const float4* fs = (const float4*)(g_fs0 + (size_t)src[e] * HD0);
    const float4* fd = (const float4*)(g_fd0 + (size_t)dst[e] * HD0);
    const float4* a4 = (const float4*)a0;
    float partial = 0.f;
#pragma unroll
    for (int q = 0; q < 2; q++) {
        int i4 = t * 2 + q;
        float4 u = fs[i4], v = fd[i4], w = a4[i4];
        partial = fmaf(lrelu(u.x + v.x), w.x, partial);
        partial = fmaf(lrelu(u.y + v.y), w.y, partial);
        partial = fmaf(lrelu(u.z + v.z), w.z, partial);
        partial = fmaf(lrelu(u.w + v.w), w.w, partial);
    }
    for (int off = 16; off; off >>= 1)
        partial += __shfl_down_sync(0xffffffffu, partial, off);
    if ((t & 31) == 0) g_lg0[e * NH + (t >> 5)] = partial;
}

__global__ void gatv2Agg0Kernel(const int* __restrict__ src,
                                const float* __restrict__ b0) {
    int n = blockIdx.x;
    int t = threadIdx.x;  // 256
    int h = t >> 6;
    int s = g_csr_off[n], e1 = g_csr_off[n + 1];
    float4 acc = make_float4(0.f, 0.f, 0.f, 0.f);
    for (int p = s; p < e1; p++) {
        int e = g_csr_edge[p];
        float a = g_lg0[e * NH + h];
        float4 v = ((const float4*)(g_fs0 + (size_t)src[e] * HD0))[t];
        acc.x = fmaf(a, v.x, acc.x);
        acc.y = fmaf(a, v.y, acc.y);
        acc.z = fmaf(a, v.z, acc.z);
        acc.w = fmaf(a, v.w, acc.w);
    }
    float4 r = ((const float4*)(g_res0 + (size_t)n * HD0))[t];
    float4 bb = ((const float4*)b0)[t];
    acc.x = fmaxf(acc.x + r.x + bb.x, 0.f);
    acc.y = fmaxf(acc.y + r.y + bb.y, 0.f);
    acc.z = fmaxf(acc.z + r.z + bb.z, 0.f);
    acc.w = fmaxf(acc.w + r.w + bb.w, 0.f);
    ((float4*)(g_x1 + (size_t)n * HD0))[t] = acc;
}

// ------------------- gatv2 layer 1 (D=8) --------------------------------------
__global__ void gatv2EdgeLogits1Kernel(const int* __restrict__ src,
                                       const int* __restrict__ dst,
                                       const float* __restrict__ a1) {
    int w = (blockIdx.x * blockDim.x + threadIdx.x) >> 5;
    int lane = threadIdx.x & 31;
    if (w >= NEDGES) return;
    float x = g_l1out[(size_t)src[w] * L1W + lane] +
              g_l1out[(size_t)dst[w] * L1W + HD1 + lane];
    float p = lrelu(x) * a1[lane];
    p += __shfl_down_sync(0xffffffffu, p, 4, 8);
    p += __shfl_down_sync(0xffffffffu, p, 2, 8);
    p += __shfl_down_sync(0xffffffffu, p, 1, 8);
    if ((lane & 7) == 0) g_lg1[w * NH + (lane >> 3)] = p;
}

// ------------------- final linear ---------------------------------------------
__global__ void finalLinearKernel(const float* __restrict__ Wlin,
                                  const float* __restrict__ blin,
                                  float* __restrict__ out) {
    int n = blockIdx.x * 256 + threadIdx.x;
    if (n >= NNODES) return;
    float acc[OUTD];
#pragma unroll
    for (int c = 0; c < OUTD; c++) acc[c] = blin[c];
#pragma unroll 4
    for (int j = 0; j < HD1; j++) {
        float v = g_h3[n * HD1 + j];
#pragma unroll
        for (int c = 0; c < OUTD; c++) acc[c] = fmaf(v, Wlin[j * OUTD + c], acc[c]);
    }
#pragma unroll 4
    for (int j = 0; j < HD1; j++) {
        float v = g_out1[n * HD1 + j];
#pragma unroll
        for (int c = 0; c < OUTD; c++)
            acc[c] = fmaf(v, Wlin[(HD1 + j) * OUTD + c], acc[c]);
    }
#pragma unroll
    for (int c = 0; c < OUTD; c++) out[n * OUTD + c] = acc[c];
}

// ------------------- launch ---------------------------------------------------
extern "C" void kernel_launch(void* const* d_in, const int* in_sizes, int n_in,
                              void* d_out, int out_size) {
    const float* features = (const float*)d_in[0];
    const int* src = (const int*)d_in[1];
    const int* dst = (const int*)d_in[2];
    const float* textMask = (const float*)d_in[3];
    const float* audioMask = (const float*)d_in[4];
    const float* videoMask = (const float*)d_in[5];
    const float* W2 = (const float*)d_in[6];
    const float* a2 = (const float*)d_in[7];
    const float* Wl0 = (const float*)d_in[8];
    const float* Wr0 = (const float*)d_in[9];
    const float* a0 = (const float*)d_in[10];
    const float* Wres0 = (const float*)d_in[11];
    const float* b0 = (const float*)d_in[12];
    const float* Wl1 = (const float*)d_in[13];
    const float* Wr1 = (const float*)d_in[14];
    const float* a1 = (const float*)d_in[15];
    const float* Wres1 = (const float*)d_in[16];
    const float* b1 = (const float*)d_in[17];
    const float* Wlin = (const float*)d_in[18];
    const float* blin = (const float*)d_in[19];
    float* out = (float*)d_out;

    float *p_h, *p_fs0, *p_fd0, *p_res0, *p_x1, *p_z2, *p_l1out;
    float *p_W2p, *p_Wcat, *p_lg0, *p_lg1, *p_lg2, *p_h3, *p_out1;
    cudaGetSymbolAddress((void**)&p_h, g_h);
    cudaGetSymbolAddress((void**)&p_fs0, g_fs0);
    cudaGetSymbolAddress((void**)&p_fd0, g_fd0);
    cudaGetSymbolAddress((void**)&p_res0, g_res0);
    cudaGetSymbolAddress((void**)&p_x1, g_x1);
    cudaGetSymbolAddress((void**)&p_z2, g_z2);
    cudaGetSymbolAddress((void**)&p_l1out, g_l1out);
    cudaGetSymbolAddress((void**)&p_W2p, g_W2p);
    cudaGetSymbolAddress((void**)&p_Wcat, g_Wcat);
    cudaGetSymbolAddress((void**)&p_lg0, g_lg0);
    cudaGetSymbolAddress((void**)&p_lg1, g_lg1);
    cudaGetSymbolAddress((void**)&p_lg2, g_lg2);
    cudaGetSymbolAddress((void**)&p_h3, g_h3);
    cudaGetSymbolAddress((void**)&p_out1, g_out1);

    // allow 72KB dynamic smem for the GEMM (host-side, capture-time only)
    cudaFuncSetAttribute(tf32GemmKernel,
                         cudaFuncAttributeMaxDynamicSharedMemorySize,
                         (int)GEMM_SMEM);

    // 1) preprocessing (launch order puts first big GEMM at profiled slot)
    zeroKernel<<<(NNODES + 255) / 256, 256>>>();
    {
        dim3 g((IN_DIM + 255) / 256, 40);
        colsumKernel<<<g, 256>>>(features);
    }
    preprocessKernel<<<NNODES, 256>>>(features, textMask, audioMask, videoMask);

    // 2) big GEMMs (tf32 tensor): [10000 x 1247] x [1247 x 1024]
    {
        dim3 g((NNODES + BMt - 1) / BMt, (HD0 + BNt - 1) / BNt);
        tf32GemmKernel<<<g, 256, GEMM_SMEM>>>(p_h, IN_DIM, Wl0, HD0, p_fs0, HD0, NNODES, HD0);
        tf32GemmKernel<<<g, 256, GEMM_SMEM>>>(p_h, IN_DIM, Wr0, HD0, p_fd0, HD0, NNODES, HD0);
        tf32GemmKernel<<<g, 256, GEMM_SMEM>>>(p_h, IN_DIM, Wres0, HD0, p_res0, HD0, NNODES, HD0);
    }

    // 3) packing + CSR build
    packW2Kernel<<<(IN_DIM * HD1 + 255) / 256, 256>>>(W2);
    packWcatKernel<<<(HD0 * L1W + 255) / 256, 256>>>(Wl1, Wr1, Wres1);
    histKernel<<<(NEDGES + 255) / 256, 256>>>(dst);
    scanKernel<<<1, 1024>>>();
    fillCsrKernel<<<(NEDGES + 255) / 256, 256>>>(dst);

    // z2 = h @ W2packed : [10000 x 1247] x [1247 x 32]
    {
        dim3 g((NNODES + BMt - 1) / BMt, 1);
        tf32GemmKernel<<<g, 256, GEMM_SMEM>>>(p_h, IN_DIM, p_W2p, HD1, p_z2, HD1, NNODES, HD1);
    }

    // 4) gat_inner -> h3
    innerNodeTermsKernel<<<(NNODES * NH + 255) / 256, 256>>>(a2);
    innerEdgeLogitsKernel<<<(NEDGES * NH + 255) / 256, 256>>>(src, dst);
    segSoftmaxKernel<<<(NNODES * NH + 255) / 256, 256>>>(p_lg2);
    aggSmallKernel<<<(NNODES * 32 + 255) / 256, 256>>>(p_z2, HD1, p_lg2, src,
                                                       (const float*)0, 0,
                                                       (const float*)0, p_h3, 0);

    // 5) gatv2 layer 0 -> x1
    gatv2EdgeLogits0Kernel<<<NEDGES, 128>>>(src, dst, a0);
    segSoftmaxKernel<<<(NNODES * NH + 255) / 256, 256>>>(p_lg0);
    gatv2Agg0Kernel<<<NNODES, 256>>>(src, b0);

    // 6) layer-1 projections fused: [10000 x 1024] x [1024 x 96]
    {
        dim3 g((NNODES + BMt - 1) / BMt, 1);
        tf32GemmKernel<<<g, 256, GEMM_SMEM>>>(p_x1, HD0, p_Wcat, L1W, p_l1out, L1W, NNODES, L1W);
    }

    // 7) gatv2 layer 1 -> out1
    gatv2EdgeLogits1Kernel<<<(NEDGES * 32 + 255) / 256, 256>>>(src, dst, a1);
    segSoftmaxKernel<<<(NNODES * NH + 255) / 256, 256>>>(p_lg1);
    aggSmallKernel<<<(NNODES * 32 + 255) / 256, 256>>>(p_l1out, L1W, p_lg1, src,
                                                       p_l1out + 2 * HD1, L1W, b1,
                                                       p_out1, 1);

    // 8) final linear
    finalLinearKernel<<<(NNODES + 255) / 256, 256>>>(Wlin, blin, out);
}

// round 6
// speedup vs baseline: 4.5494x; 2.1725x over previous
#include <cuda_runtime.h>
#include <math.h>
#include <stdint.h>

#define NNODES 10000
#define NEDGES 64000
#define IN_DIM 1247
#define KPAD   1280          /* IN_DIM padded to 40 k-tiles */
#define NKT0   40            /* KPAD/32 */
#define NKT1   32            /* 1024/32 */
#define NRT    79            /* ceil(10000/128) row tiles */
#define MPAD   (NRT * 128)   /* 10112 */
#define NH 4
#define DD0 256
#define DD1 8
#define OUTD 6
#define HD0 1024
#define HD1 32
#define NBIG 3104            /* 1024*3 + 32 (z2) */
#define NCT0 25              /* ceil(3104/128) col tiles */
#define L1W 96

// ------------------- scratch (device globals) --------------------------------
__device__ __align__(16) float g_colsum[IN_DIM];
__device__ __align__(16) float g_hA[(size_t)NRT * NKT0 * 4096];    /* A tiles, tf32 */
__device__ __align__(16) float g_WbigT[(size_t)NCT0 * NKT0 * 4096];/* B tiles, tf32 */
__device__ __align__(16) float g_WcatT[(size_t)1 * NKT1 * 4096];   /* layer1 B tiles */
__device__ __align__(16) float g_big[(size_t)NNODES * NBIG];       /* fs0|fd0|res0|z2 */
__device__ __align__(16) float g_x1A[(size_t)NRT * NKT1 * 4096];   /* x1 A tiles, tf32 */
__device__ __align__(16) float g_l1out[(size_t)NNODES * L1W];
__device__ __align__(16) float g_h3[NNODES * HD1];
__device__ __align__(16) float g_out1[NNODES * HD1];
__device__ float g_es2[NNODES * NH];
__device__ float g_ed2[NNODES * NH];
__device__ float g_lg0[NEDGES * NH];
__device__ float g_lg1[NEDGES * NH];
__device__ float g_lg2[NEDGES * NH];
__device__ int   g_deg[NNODES];
__device__ int   g_fill[NNODES];
__device__ int   g_csr_off[NNODES + 1];
__device__ int   g_csr_edge[NEDGES];

__device__ __forceinline__ float lrelu(float x) { return x > 0.f ? x : 0.2f * x; }
__device__ __forceinline__ float to_tf32(float x) {
    float r; asm("cvt.rna.tf32.f32 %0, %1;" : "=f"(r) : "f"(x)); return r;
}
__device__ __forceinline__ uint32_t fau(float x) { return __float_as_uint(x); }
// packed-tile element offset for (row r in tile, local k)
__device__ __forceinline__ int tileOff(int r, int kl) {
    int ck = ((kl & 3) << 3) | (kl >> 2);
    int chunk = (ck >> 2) ^ (r & 7);
    return (r << 5) + (chunk << 2) + (ck & 3);
}
__device__ __forceinline__ void cp16(uint32_t s, const float* g) {
    asm volatile("cp.async.cg.shared.global [%0], [%1], 16;" :: "r"(s), "l"(g));
}

// ------------------- preprocessing ------------------------------------------
__global__ void zeroKernel() {
    int i = blockIdx.x * 256 + threadIdx.x;
    if (i < IN_DIM) g_colsum[i] = 0.f;
    if (i < NNODES) { g_deg[i] = 0; g_fill[i] = 0; }
}

__global__ void colsumKernel(const float* __restrict__ f) {
    int j = blockIdx.x * 256 + threadIdx.x;
    if (j >= IN_DIM) return;
    float s = 0.f;
    for (int i = blockIdx.y; i < NNODES; i += gridDim.y)
        s += f[(size_t)i * IN_DIM + j];
    atomicAdd(&g_colsum[j], s);
}

// impute+normalize+mask, then emit tf32 into packed A-tile layout (K padded)
__global__ void preprocessKernel(const float* __restrict__ f,
                                 const float* __restrict__ tm,
                                 const float* __restrict__ am,
                                 const float* __restrict__ vm) {
    __shared__ float sh[IN_DIM];
    __shared__ float red[8];
    int n = blockIdx.x;            // 0..MPAD-1
    int t = threadIdx.x;
    int r = n & 127, rt = n >> 7;
    float* base = g_hA + ((size_t)rt * NKT0 << 12);
    if (n >= NNODES) {
        for (int j = t; j < KPAD; j += 256) {
            int kt = j >> 5;
            base[(kt << 12) + tileOff(r, j & 31)] = 0.f;
        }
        return;
    }
    const float* row = f + (size_t)n * IN_DIM;
    const float invN = 1.f / (float)NNODES;
    float s = 0.f;
    for (int j = t; j < IN_DIM; j += 256) {
        float v = row[j];
        v = (v == 0.f) ? (0.5f * g_colsum[j] * invN) : v;
        sh[j] = v;
        s += fabsf(v);
    }
    for (int off = 16; off; off >>= 1) s += __shfl_down_sync(0xffffffffu, s, off);
    if ((t & 31) == 0) red[t >> 5] = s;
    __syncthreads();
    if (t == 0) {
        float tot = 0.f;
        for (int w = 0; w < 8; w++) tot += red[w];
        red[0] = 1.f / fmaxf(tot, 1e-12f);
    }
    __syncthreads();
    float inv = red[0];
    for (int j = t; j < KPAD; j += 256) {
        float v = 0.f;
        if (j < IN_DIM) v = to_tf32(sh[j] * inv * (tm[j] + am[j] + vm[j]));
        int kt = j >> 5;
        base[(kt << 12) + tileOff(r, j & 31)] = v;
    }
}

// build g_WbigT: columns [Wl0 | Wr0 | Wres0 | W2packed | 0], rows k<IN_DIM, tf32
__global__ void packWbigTKernel(const float* __restrict__ Wl0,
                                const float* __restrict__ Wr0,
                                const float* __restrict__ Wres0,
                                const float* __restrict__ W2) {
    int i = blockIdx.x * 256 + threadIdx.x;
    if (i >= NCT0 * NKT0 * 4096) return;
    int ct = i / (NKT0 * 4096);
    int rem = i % (NKT0 * 4096);
    int kt = rem >> 12;
    int p = rem & 4095;
    int r = p >> 5, pos = p & 31;
    int chunk = (pos >> 2) ^ (r & 7);
    int ck = (chunk << 2) | (pos & 3);
    int kl = ((ck & 7) << 2) | (ck >> 3);
    int k = kt * 32 + kl;
    int n = ct * 128 + r;
    float v = 0.f;
    if (k < IN_DIM) {
        if (n < HD0) v = Wl0[(size_t)k * HD0 + n];
        else if (n < 2 * HD0) v = Wr0[(size_t)k * HD0 + (n - HD0)];
        else if (n < 3 * HD0) v = Wres0[(size_t)k * HD0 + (n - 2 * HD0)];
        else if (n < 3 * HD0 + HD1) {
            int c = n - 3 * HD0;
            v = W2[((size_t)(c >> 3) * IN_DIM + k) * DD1 + (c & 7)];
        }
    }
    g_WbigT[i] = to_tf32(v);
}

// build g_WcatT: columns [Wl1 | Wr1 | Wres1 | 0], K=1024, tf32
__global__ void packWcatTKernel(const float* __restrict__ Wl1,
                                const float* __restrict__ Wr1,
                                const float* __restrict__ Wres1) {
    int i = blockIdx.x * 256 + threadIdx.x;
    if (i >= NKT1 * 4096) return;
    int kt = i >> 12;
    int p = i & 4095;
    int r = p >> 5, pos = p & 31;
    int chunk = (pos >> 2) ^ (r & 7);
    int ck = (chunk << 2) | (pos & 3);
    int kl = ((ck & 7) << 2) | (ck >> 3);
    int k = kt * 32 + kl;
    int n = r;
    float v = 0.f;
    if (n < HD1) v = Wl1[(size_t)k * HD1 + n];
    else if (n < 2 * HD1) v = Wr1[(size_t)k * HD1 + (n - HD1)];
    else if (n < L1W) v = Wres1[(size_t)k * HD1 + (n - 2 * HD1)];
    g_WcatT[i] = to_tf32(v);
}

// ------------------- CSR build ----------------------------------------------
__global__ void histKernel(const int* __restrict__ dst) {
    int e = blockIdx.x * 256 + threadIdx.x;
    if (e < NEDGES) atomicAdd(&g_deg[dst[e]], 1);
}

__global__ void scanKernel() {
    __shared__ int sums[1024];
    const int CH = (NNODES + 1023) / 1024;
    int t = threadIdx.x;
    int base = t * CH;
    int local[CH];
    int s = 0;
    for (int i = 0; i < CH; i++) {
        int v = (base + i < NNODES) ? g_deg[base + i] : 0;
        local[i] = s;
        s += v;
    }
    sums[t] = s;
    __syncthreads();
    for (int off = 1; off < 1024; off <<= 1) {
        int v = (t >= off) ? sums[t - off] : 0;
        __syncthreads();
        sums[t] += v;
        __syncthreads();
    }
    int excl = (t == 0) ? 0 : sums[t - 1];
    for (int i = 0; i < CH; i++)
        if (base + i < NNODES) g_csr_off[base + i] = excl + local[i];
    if (t == 1023) g_csr_off[NNODES] = sums[1023];
}

__global__ void fillCsrKernel(const int* __restrict__ dst) {
    int e = blockIdx.x * 256 + threadIdx.x;
    if (e >= NEDGES) return;
    int d = dst[e];
    int pos = atomicAdd(&g_fill[d], 1);
    g_csr_edge[g_csr_off[d] + pos] = e;
}

// ------------------- TF32 tensor GEMM on pre-packed tiles --------------------
// Apack: [gridDim.x][nKt][4096] tiles (tf32, swizzled); Bpack: [gridDim.y][nKt][4096].
// C row-major [Mrows x ldc]; stores guarded by Mrows/Ncols.
#define GEMM_SMEM (16384 * sizeof(float))

__global__ __launch_bounds__(256, 2) void tf32GemmKernel(
    const float* __restrict__ Apack, const float* __restrict__ Bpack,
    int nKt, float* __restrict__ C, int ldc, int Mrows, int Ncols) {
    extern __shared__ float sm[];
    int tid = threadIdx.x;
    int lane = tid & 31;
    int w = tid >> 5;
    int wm = w & 1, wn = w >> 1;
    int g = lane >> 2, tg = lane & 3;
    int r0 = blockIdx.x * 128, c0 = blockIdx.y * 128;

    const float* gA = Apack + ((size_t)blockIdx.x * nKt << 12);
    const float* gB = Bpack + ((size_t)blockIdx.y * nKt << 12);
    uint32_t sbase = (uint32_t)__cvta_generic_to_shared(sm);
    uint32_t sA[2] = {sbase, sbase + 16384u};
    uint32_t sB[2] = {sbase + 32768u, sbase + 49152u};

    float acc[4][4][4];
#pragma unroll
    for (int i = 0; i < 4; i++)
#pragma unroll
        for (int j = 0; j < 4; j++)
#pragma unroll
            for (int r = 0; r < 4; r++) acc[i][j][r] = 0.f;

    // prologue: tile 0
#pragma unroll
    for (int s = 0; s < 4; s++) {
        int i = s * 256 + tid;
        cp16(sA[0] + i * 16, gA + i * 4);
        cp16(sB[0] + i * 16, gB + i * 4);
    }
    asm volatile("cp.async.commit_group;" ::: "memory");

    for (int kt = 0; kt < nKt; kt++) {
        int buf = kt & 1;
        bool hasNext = (kt + 1) < nKt;
        if (hasNext) {
            const float* nA = gA + ((size_t)(kt + 1) << 12);
            const float* nB = gB + ((size_t)(kt + 1) << 12);
            int nb = buf ^ 1;
#pragma unroll
            for (int s = 0; s < 4; s++) {
                int i = s * 256 + tid;
                cp16(sA[nb] + i * 16, nA + i * 4);
                cp16(sB[nb] + i * 16, nB + i * 4);
            }
            asm volatile("cp.async.commit_group;" ::: "memory");
            asm volatile("cp.async.wait_group 1;" ::: "memory");
        } else {
            asm volatile("cp.async.wait_group 0;" ::: "memory");
        }
        __syncthreads();

        const float* As = sm + (buf ? 4096 : 0);
        const float* Bs = sm + 8192 + (buf ? 4096 : 0);
#pragma unroll
        for (int half = 0; half < 2; half++) {
            int chunk = ((tg << 1) + half) ^ g;      // same for all fragments
            int coff = chunk << 2;
            float4 Af0[4], Af1[4], Bf[4];
#pragma unroll
            for (int mf = 0; mf < 4; mf++) {
                int r = wm * 64 + mf * 16 + g;
                Af0[mf] = *(const float4*)(As + (r << 5) + coff);
                Af1[mf] = *(const float4*)(As + ((r + 8) << 5) + coff);
            }
#pragma unroll
            for (int nf = 0; nf < 4; nf++) {
                int cc = wn * 32 + nf * 8 + g;
                Bf[nf] = *(const float4*)(Bs + (cc << 5) + coff);
            }
#pragma unroll
            for (int ks2 = 0; ks2 < 2; ks2++) {
#pragma unroll
                for (int mf = 0; mf < 4; mf++) {
                    uint32_t a0, a1, a2, a3;
                    if (ks2 == 0) {
                        a0 = fau(Af0[mf].x); a1 = fau(Af1[mf].x);
                        a2 = fau(Af0[mf].y); a3 = fau(Af1[mf].y);
                    } else {
                        a0 = fau(Af0[mf].z); a1 = fau(Af1[mf].z);
                        a2 = fau(Af0[mf].w); a3 = fau(Af1[mf].w);
                    }
#pragma unroll
                    for (int nf = 0; nf < 4; nf++) {
                        uint32_t b0 = (ks2 == 0) ? fau(Bf[nf].x) : fau(Bf[nf].z);
                        uint32_t b1 = (ks2 == 0) ? fau(Bf[nf].y) : fau(Bf[nf].w);
                        asm volatile(
                            "mma.sync.aligned.m16n8k8.row.col.f32.tf32.tf32.f32 "
                            "{%0,%1,%2,%3}, {%4,%5,%6,%7}, {%8,%9}, {%0,%1,%2,%3};"
                            : "+f"(acc[mf][nf][0]), "+f"(acc[mf][nf][1]),
                              "+f"(acc[mf][nf][2]), "+f"(acc[mf][nf][3])
                            : "r"(a0), "r"(a1), "r"(a2), "r"(a3),
                              "r"(b0), "r"(b1));
                    }
                }
            }
        }
        __syncthreads();
    }

    // epilogue
#pragma unroll
    for (int mf = 0; mf < 4; mf++) {
        int rA = r0 + wm * 64 + mf * 16 + g;
        int rB = rA + 8;
#pragma unroll
        for (int nf = 0; nf < 4; nf++) {
            int gc = c0 + wn * 32 + nf * 8 + tg * 2;
            if (gc < Ncols) {
                if (rA < Mrows) C[(size_t)rA * ldc + gc] = acc[mf][nf][0];
                if (rB < Mrows) C[(size_t)rB * ldc + gc] = acc[mf][nf][2];
            }
            if (gc + 1 < Ncols) {
                if (rA < Mrows) C[(size_t)rA * ldc + gc + 1] = acc[mf][nf][1];
                if (rB < Mrows) C[(size_t)rB * ldc + gc + 1] = acc[mf][nf][3];
            }
        }
    }
}

// ------------------- gat_inner (h3) ------------------------------------------
__global__ void innerNodeTermsKernel(const float* __restrict__ a2) {
    int idx = blockIdx.x * 256 + threadIdx.x;
    if (idx >= NNODES * NH) return;
    int n = idx / NH, h = idx % NH;
    const float* z = g_big + (size_t)n * NBIG + 3 * HD0 + h * DD1;
    float es = 0.f, ed = 0.f;
#pragma unroll
    for (int o = 0; o < DD1; o++) {
        es = fmaf(z[o], a2[h * 2 * DD1 + o], es);
        ed = fmaf(z[o], a2[h * 2 * DD1 + DD1 + o], ed);
    }
    g_es2[idx] = es;
    g_ed2[idx] = ed;
}

__global__ void innerEdgeLogitsKernel(const int* __restrict__ src,
                                      const int* __restrict__ dst) {
    int idx = blockIdx.x * 256 + threadIdx.x;
    if (idx >= NEDGES * NH) return;
    int e = idx / NH, h = idx % NH;
    g_lg2[idx] = lrelu(g_es2[src[e] * NH + h] + g_ed2[dst[e] * NH + h]);
}

__global__ void segSoftmaxKernel(float* __restrict__ lg) {
    int idx = blockIdx.x * 256 + threadIdx.x;
    if (idx >= NNODES * NH) return;
    int n = idx / NH, h = idx % NH;
    int s = g_csr_off[n], t = g_csr_off[n + 1];
    float m = -1e30f;
    for (int p = s; p < t; p++) m = fmaxf(m, lg[g_csr_edge[p] * NH + h]);
    float den = 0.f;
    for (int p = s; p < t; p++) {
        int a = g_csr_edge[p] * NH + h;
        float pv = __expf(lg[a] - m);
        den += pv;
        lg[a] = pv;
    }
    float inv = 1.f / fmaxf(den, 1e-9f);
    for (int p = s; p < t; p++) lg[g_csr_edge[p] * NH + h] *= inv;
}

__global__ void aggSmallKernel(const float* __restrict__ vals, int vstride,
                               const float* __restrict__ lg,
                               const int* __restrict__ src,
                               const float* __restrict__ res, int rstride,
                               const float* __restrict__ bias,
                               float* __restrict__ out, int doRelu) {
    int w = (blockIdx.x * blockDim.x + threadIdx.x) >> 5;
    int lane = threadIdx.x & 31;
    if (w >= NNODES) return;
    int h = lane >> 3;
    int s = g_csr_off[w], t = g_csr_off[w + 1];
    float acc = 0.f;
    for (int p = s; p < t; p++) {
        int e = g_csr_edge[p];
        acc = fmaf(lg[e * NH + h], vals[(size_t)src[e] * vstride + lane], acc);
    }
    if (res) acc += res[(size_t)w * rstride + lane] + bias[lane];
    if (doRelu) acc = fmaxf(acc, 0.f);
    out[w * HD1 + lane] = acc;
}

// ------------------- gatv2 layer 0 (D=256) ------------------------------------
__global__ void gatv2EdgeLogits0Kernel(const int* __restrict__ src,
                                       const int* __restrict__ dst,
                                       const float* __restrict__ a0) {
    int e = blockIdx.x;
    int t = threadIdx.x;  // 128
    const float4* fs = (const float4*)(g_big + (size_t)src[e] * NBIG);
    const float4* fd = (const float4*)(g_big + (size_t)dst[e] * NBIG + HD0);
    const float4* a4 = (const float4*)a0;
    float partial = 0.f;
#pragma unroll
    for (int q = 0; q < 2; q++) {
        int i4 = t * 2 + q;
        float4 u = fs[i4], v = fd[i4], w = a4[i4];
        partial = fmaf(lrelu(u.x + v.x), w.x, partial);
        partial = fmaf(lrelu(u.y + v.y), w.y, partial);
        partial = fmaf(lrelu(u.z + v.z), w.z, partial);
        partial = fmaf(lrelu(u.w + v.w), w.w, partial);
    }
    for (int off = 16; off; off >>= 1)
        partial += __shfl_down_sync(0xffffffffu, partial, off);
    if ((t & 31) == 0) g_lg0[e * NH + (t >> 5)] = partial;
}

// aggregate layer-0, add residual+bias, relu; write x1 as packed tf32 A-tiles
__global__ void gatv2Agg0Kernel(const int* __restrict__ src,
                                const float* __restrict__ b0) {
    int n = blockIdx.x;            // 0..MPAD-1
    int t = threadIdx.x;           // 256; 4 consecutive k each
    int r = n & 127, rt = n >> 7;
    float* base = g_x1A + ((size_t)rt * NKT1 << 12);
    if (n >= NNODES) {
#pragma unroll
        for (int q = 0; q < 4; q++) {
            int k = t * 4 + q;
            base[((k >> 5) << 12) + tileOff(r, k & 31)] = 0.f;
        }
        return;
    }
    int h = t >> 6;
    int s = g_csr_off[n], e1 = g_csr_off[n + 1];
    float4 acc = make_float4(0.f, 0.f, 0.f, 0.f);
    for (int p = s; p < e1; p++) {
        int e = g_csr_edge[p];
        float a = g_lg0[e * NH + h];
        float4 v = ((const float4*)(g_big + (size_t)src[e] * NBIG))[t];
        acc.x = fmaf(a, v.x, acc.x);
        acc.y = fmaf(a, v.y, acc.y);
        acc.z = fmaf(a, v.z, acc.z);
        acc.w = fmaf(a, v.w, acc.w);
    }
    float4 rr = ((const float4*)(g_big + (size_t)n * NBIG + 2 * HD0))[t];
    float4 bb = ((const float4*)b0)[t];
    float o[4];
    o[0] = fmaxf(acc.x + rr.x + bb.x, 0.f);
    o[1] = fmaxf(acc.y + rr.y + bb.y, 0.f);
    o[2] = fmaxf(acc.z + rr.z + bb.z, 0.f);
    o[3] = fmaxf(acc.w + rr.w + bb.w, 0.f);
#pragma unroll
    for (int q = 0; q < 4; q++) {
        int k = t * 4 + q;
        base[((k >> 5) << 12) + tileOff(r, k & 31)] = to_tf32(o[q]);
    }
}

// ------------------- gatv2 layer 1 (D=8) --------------------------------------
__global__ void gatv2EdgeLogits1Kernel(const int* __restrict__ src,
                                       const int* __restrict__ dst,
                                       const float* __restrict__ a1) {
    int w = (blockIdx.x * blockDim.x + threadIdx.x) >> 5;
    int lane = threadIdx.x & 31;
    if (w >= NEDGES) return;
    float x = g_l1out[(size_t)src[w] * L1W + lane] +
              g_l1out[(size_t)dst[w] * L1W + HD1 + lane];
    float p = lrelu(x) * a1[lane];
    p += __shfl_down_sync(0xffffffffu, p, 4, 8);
    p += __shfl_down_sync(0xffffffffu, p, 2, 8);
    p += __shfl_down_sync(0xffffffffu, p, 1, 8);
    if ((lane & 7) == 0) g_lg1[w * NH + (lane >> 3)] = p;
}

// ------------------- final linear ---------------------------------------------
__global__ void finalLinearKernel(const float* __restrict__ Wlin,
                                  const float* __restrict__ blin,
                                  float* __restrict__ out) {
    int n = blockIdx.x * 256 + threadIdx.x;
    if (n >= NNODES) return;
    float acc[OUTD];
#pragma unroll
    for (int c = 0; c < OUTD; c++) acc[c] = blin[c];
#pragma unroll 4
    for (int j = 0; j < HD1; j++) {
        float v = g_h3[n * HD1 + j];
#pragma unroll
        for (int c = 0; c < OUTD; c++) acc[c] = fmaf(v, Wlin[j * OUTD + c], acc[c]);
    }
#pragma unroll 4
    for (int j = 0; j < HD1; j++) {
        float v = g_out1[n * HD1 + j];
#pragma unroll
        for (int c = 0; c < OUTD; c++)
            acc[c] = fmaf(v, Wlin[(HD1 + j) * OUTD + c], acc[c]);
    }
#pragma unroll
    for (int c = 0; c < OUTD; c++) out[n * OUTD + c] = acc[c];
}

// ------------------- launch ---------------------------------------------------
extern "C" void kernel_launch(void* const* d_in, const int* in_sizes, int n_in,
                              void* d_out, int out_size) {
    const float* features = (const float*)d_in[0];
    const int* src = (const int*)d_in[1];
    const int* dst = (const int*)d_in[2];
    const float* textMask = (const float*)d_in[3];
    const float* audioMask = (const float*)d_in[4];
    const float* videoMask = (const float*)d_in[5];
    const float* W2 = (const float*)d_in[6];
    const float* a2 = (const float*)d_in[7];
    const float* Wl0 = (const float*)d_in[8];
    const float* Wr0 = (const float*)d_in[9];
    const float* a0 = (const float*)d_in[10];
    const float* Wres0 = (const float*)d_in[11];
    const float* b0 = (const float*)d_in[12];
    const float* Wl1 = (const float*)d_in[13];
    const float* Wr1 = (const float*)d_in[14];
    const float* a1 = (const float*)d_in[15];
    const float* Wres1 = (const float*)d_in[16];
    const float* b1 = (const float*)d_in[17];
    const float* Wlin = (const float*)d_in[18];
    const float* blin = (const float*)d_in[19];
    float* out = (float*)d_out;

    float *p_hA, *p_WbigT, *p_WcatT, *p_big, *p_x1A, *p_l1out;
    float *p_lg0, *p_lg1, *p_lg2, *p_h3, *p_out1;
    cudaGetSymbolAddress((void**)&p_hA, g_hA);
    cudaGetSymbolAddress((void**)&p_WbigT, g_WbigT);
    cudaGetSymbolAddress((void**)&p_WcatT, g_WcatT);
    cudaGetSymbolAddress((void**)&p_big, g_big);
    cudaGetSymbolAddress((void**)&p_x1A, g_x1A);
    cudaGetSymbolAddress((void**)&p_l1out, g_l1out);
    cudaGetSymbolAddress((void**)&p_lg0, g_lg0);
    cudaGetSymbolAddress((void**)&p_lg1, g_lg1);
    cudaGetSymbolAddress((void**)&p_lg2, g_lg2);
    cudaGetSymbolAddress((void**)&p_h3, g_h3);
    cudaGetSymbolAddress((void**)&p_out1, g_out1);

    cudaFuncSetAttribute(tf32GemmKernel,
                         cudaFuncAttributeMaxDynamicSharedMemorySize,
                         (int)GEMM_SMEM);

    // 0-2) preprocessing (+ packed-A emit)
    zeroKernel<<<(NNODES + 255) / 256, 256>>>();
    {
        dim3 g((IN_DIM + 255) / 256, 40);
        colsumKernel<<<g, 256>>>(features);
    }
    preprocessKernel<<<MPAD, 256>>>(features, textMask, audioMask, videoMask);

    // 3-4) weight packs
    packWbigTKernel<<<(NCT0 * NKT0 * 4096 + 255) / 256, 256>>>(Wl0, Wr0, Wres0, W2);
    packWcatTKernel<<<(NKT1 * 4096 + 255) / 256, 256>>>(Wl1, Wr1, Wres1);

    // 5) fused big GEMM: [10112 x 1280] x [1280 x 3200] -> g_big [10000 x 3104]
    {
        dim3 g(NRT, NCT0);
        tf32GemmKernel<<<g, 256, GEMM_SMEM>>>(p_hA, p_WbigT, NKT0, p_big, NBIG,
                                              NNODES, NBIG);
    }

    // CSR build
    histKernel<<<(NEDGES + 255) / 256, 256>>>(dst);
    scanKernel<<<1, 1024>>>();
    fillCsrKernel<<<(NEDGES + 255) / 256, 256>>>(dst);

    // gat_inner -> h3  (z2 = g_big cols 3072..3103)
    innerNodeTermsKernel<<<(NNODES * NH + 255) / 256, 256>>>(a2);
    innerEdgeLogitsKernel<<<(NEDGES * NH + 255) / 256, 256>>>(src, dst);
    segSoftmaxKernel<<<(NNODES * NH + 255) / 256, 256>>>(p_lg2);
    aggSmallKernel<<<(NNODES * 32 + 255) / 256, 256>>>(p_big + 3 * HD0, NBIG, p_lg2,
                                                       src, (const float*)0, 0,
                                                       (const float*)0, p_h3, 0);

    // gatv2 layer 0 -> x1 (packed)
    gatv2EdgeLogits0Kernel<<<NEDGES, 128>>>(src, dst, a0);
    segSoftmaxKernel<<<(NNODES * NH + 255) / 256, 256>>>(p_lg0);
    gatv2Agg0Kernel<<<MPAD, 256>>>(src, b0);

    // layer-1 projections fused: [10112 x 1024] x [1024 x 128] -> g_l1out [10000 x 96]
    {
        dim3 g(NRT, 1);
        tf32GemmKernel<<<g, 256, GEMM_SMEM>>>(p_x1A, p_WcatT, NKT1, p_l1out, L1W,
                                              NNODES, L1W);
    }

    // gatv2 layer 1 -> out1
    gatv2EdgeLogits1Kernel<<<(NEDGES * 32 + 255) / 256, 256>>>(src, dst, a1);
    segSoftmaxKernel<<<(NNODES * NH + 255) / 256, 256>>>(p_lg1);
    aggSmallKernel<<<(NNODES * 32 + 255) / 256, 256>>>(p_l1out, L1W, p_lg1, src,
                                                       p_l1out + 2 * HD1, L1W, b1,
                                                       p_out1, 1);

    // final linear
    finalLinearKernel<<<(NNODES + 255) / 256, 256>>>(Wlin, blin, out);
}